// round 11
// baseline (speedup 1.0000x reference)
#include <cuda_runtime.h>
#include <cuda_fp16.h>
#include <cstdint>

#define B_SZ    8
#define L_SEQ   4096
#define D_MODEL 512
#define D_INNER 1024
#define NHEADS  16
#define HEADDIM 64
#define D_STATE 16
#define CONV_DIM 1056
#define D_IN_PROJ 2096
#define BL      (B_SZ * L_SEQ)
#define CS      64
#define NC      (L_SEQ / CS)
#define AUXZ    ((size_t)BL * 16)

// ---------------- scratch (device globals; no allocation allowed) ----------------
__device__ __half g_zx16[2][(size_t)BL * D_IN_PROJ];   // in_proj out (fp16)
__device__ float g_dtraw[2][(size_t)BL * 16];          // dt pre-softplus (fp32)
__device__ float g_ssq[2][(size_t)BL * NHEADS];        // per-(row,head) sum of squares
__device__ float g_pre[(size_t)BL * D_MODEL];
__device__ float g_hstate[2][(size_t)B_SZ * NHEADS * NC * 1024];
__device__ float g_P[2][B_SZ * NHEADS * NC];

__device__ __half g_x16[(size_t)BL * D_MODEL];
__device__ __half g_wip16[2][(size_t)D_IN_PROJ * D_MODEL];
__device__ __half g_wpr16[(size_t)D_MODEL * D_INNER];
__device__ __half g_wofT16[2][(size_t)D_INNER * D_MODEL]; // out_proj^T fp16
__device__ __half g_wcomb16[(size_t)D_MODEL * 2 * D_INNER]; // [512][2048]
__device__ __half g_y16[2][(size_t)BL * D_INNER];

__device__ __forceinline__ int fliprow(int r) {
    return (r & ~(L_SEQ - 1)) | ((L_SEQ - 1) - (r & (L_SEQ - 1)));
}
__device__ __forceinline__ void cpa16(uint32_t dst, const void* src, int sz) {
    asm volatile("cp.async.cg.shared.global [%0], [%1], 16, %2;"
                 :: "r"(dst), "l"(src), "r"(sz));
}
#define CP_COMMIT() asm volatile("cp.async.commit_group;" ::: "memory")
#define CP_WAIT1()  asm volatile("cp.async.wait_group 1;" ::: "memory")

// ---------------- fp32 -> fp16 convert (grid-stride, float4) ---------------------
__global__ void f2h_kernel(const float* __restrict__ src, __half* __restrict__ dst, int n4)
{
    for (int i = blockIdx.x * blockDim.x + threadIdx.x; i < n4; i += gridDim.x * blockDim.x) {
        float4 v = *(const float4*)(src + (size_t)i * 4);
        __half2* d = (__half2*)(dst + (size_t)i * 4);
        d[0] = __floats2half2_rn(v.x, v.y);
        d[1] = __floats2half2_rn(v.z, v.w);
    }
}

// ------------- transpose fp32 [512][1024] -> fp16 [1024][512] --------------------
__global__ void tr_f2h_kernel(const float* __restrict__ s0, const float* __restrict__ s1,
                              __half* __restrict__ d0, __half* __restrict__ d1)
{
    const float* src = blockIdx.z ? s1 : s0;
    __half* dst = blockIdx.z ? d1 : d0;
    __shared__ float t[32][33];
    int c0 = blockIdx.x * 32, r0 = blockIdx.y * 32;
    int tx = threadIdx.x, ty = threadIdx.y;   // 32 x 8
    #pragma unroll
    for (int i = 0; i < 4; i++)
        t[ty + i * 8][tx] = src[(size_t)(r0 + ty + i * 8) * D_INNER + c0 + tx];
    __syncthreads();
    #pragma unroll
    for (int i = 0; i < 4; i++)
        dst[(size_t)(c0 + ty + i * 8) * D_MODEL + r0 + tx] =
            __float2half_rn(t[tx][ty + i * 8]);
}

// ============ fp16 mma.sync GEMM: C = A[M,K] @ W[N,K]^T (+bias +resid) ==========
// CTA tile 128x128, BK=64, 3-stage cp.async, 8 warps (4m x 2n), warp tile 32x64.
// grid.z selects direction set; ksplit<K enables dual-A k-stitching.
#define GT_STAGES 3
#define GT_ASZ 16384
#define GT_STG (2 * GT_ASZ)
#define GT_SMEM (GT_STAGES * GT_STG + 1024)

__global__ void __launch_bounds__(256, 2)
gemm_f16(const __half* __restrict__ A0, const __half* __restrict__ A1, int lda,
         const __half* __restrict__ W0, const __half* __restrict__ W1, int Wld,
         void* C0v, void* C1v, int ldc, int ccolstep,
         int N, int K, int ksplit,
         int flipAmask, int flipCmask, int halfOut,
         const float* __restrict__ bias,
         const float* __restrict__ resid,
         float* __restrict__ aux, int auxlo)
{
    extern __shared__ char dsm[];
    const uint32_t sb_raw = (uint32_t)__cvta_generic_to_shared(dsm);
    const uint32_t sb = (sb_raw + 1023u) & ~1023u;

    const int z = blockIdx.z;
    const int dual = (ksplit < K);
    const __half* Aa = dual ? A0 : (z ? A1 : A0);
    const __half* W = z ? W1 : W0;
    void* Cv = z ? C1v : C0v;
    const int ccol = z * ccolstep;
    const int flip_a = dual ? (flipAmask & 1) : ((flipAmask >> z) & 1);
    const int flip_b = (flipAmask >> 1) & 1;
    const int flipC = (flipCmask >> z) & 1;
    if (aux) aux += (size_t)z * AUXZ;

    const int tid = threadIdx.x;
    const int l   = tid & 31;
    const int w   = tid >> 5;
    const int wm  = w >> 1;
    const int wn  = w & 1;
    const int m0  = blockIdx.y * 128;
    const int n0  = blockIdx.x * 128;

    const int lr = l & 15;
    const int lc = l >> 4;
    const int lx = lr & 7;

    int arowA[4], arowB[4];
    #pragma unroll
    for (int i = 0; i < 4; i++) {
        int rr = (tid + i * 256) >> 3;
        int r = m0 + rr;
        arowA[i] = flip_a ? fliprow(r) : r;
        arowB[i] = flip_b ? fliprow(r) : r;
    }

    float acc[2][8][4];
    #pragma unroll
    for (int mi = 0; mi < 2; mi++)
        #pragma unroll
        for (int ni = 0; ni < 8; ni++)
            #pragma unroll
            for (int k = 0; k < 4; k++) acc[mi][ni][k] = 0.f;

    auto issue = [&](int s) {
        const int k0 = s * 64;
        const uint32_t base = sb + (s % GT_STAGES) * GT_STG;
        const __half* Ap = Aa;
        const int* ar = arowA;
        int kk = k0;
        if (dual && k0 >= ksplit) { Ap = A1; ar = arowB; kk = k0 - ksplit; }
        #pragma unroll
        for (int i = 0; i < 4; i++) {
            int q = tid + i * 256;
            int rr = q >> 3, ch = q & 7;
            int off = rr * 128 + ((ch ^ (rr & 7)) << 4);
            cpa16(base + off, Ap + (size_t)ar[i] * lda + kk + ch * 8, 16);
        }
        #pragma unroll
        for (int i = 0; i < 4; i++) {
            int q = tid + i * 256;
            int rr = q >> 3, ch = q & 7;
            int off = rr * 128 + ((ch ^ (rr & 7)) << 4);
            int n = n0 + rr;
            cpa16(base + GT_ASZ + off,
                  W + (size_t)(n < N ? n : 0) * Wld + k0 + ch * 8, (n < N) ? 16 : 0);
        }
    };
    auto compute = [&](int s) {
        const uint32_t Ab = sb + s * GT_STG;
        const uint32_t Bb = Ab + GT_ASZ;
        #pragma unroll
        for (int ks = 0; ks < 4; ks++) {
            const int chsel = ((ks << 1) | lc) ^ lx;
            uint32_t af[2][4];
            #pragma unroll
            for (int mi = 0; mi < 2; mi++) {
                uint32_t ad = Ab + (wm * 32 + mi * 16 + lr) * 128 + (chsel << 4);
                asm volatile("ldmatrix.sync.aligned.m8n8.x4.shared.b16 {%0,%1,%2,%3}, [%4];"
                    : "=r"(af[mi][0]), "=r"(af[mi][1]), "=r"(af[mi][2]), "=r"(af[mi][3])
                    : "r"(ad));
            }
            uint32_t bf[8][2];
            #pragma unroll
            for (int p = 0; p < 4; p++) {
                uint32_t bd = Bb + (wn * 64 + p * 16 + lr) * 128 + (chsel << 4);
                uint32_t q0, q1, q2, q3;
                asm volatile("ldmatrix.sync.aligned.m8n8.x4.shared.b16 {%0,%1,%2,%3}, [%4];"
                    : "=r"(q0), "=r"(q1), "=r"(q2), "=r"(q3) : "r"(bd));
                bf[2 * p][0] = q0;     bf[2 * p][1] = q2;
                bf[2 * p + 1][0] = q1; bf[2 * p + 1][1] = q3;
            }
            #pragma unroll
            for (int mi = 0; mi < 2; mi++)
                #pragma unroll
                for (int ni = 0; ni < 8; ni++) {
                    asm volatile(
                        "mma.sync.aligned.m16n8k16.row.col.f32.f16.f16.f32 "
                        "{%0,%1,%2,%3},{%4,%5,%6,%7},{%8,%9},{%0,%1,%2,%3};"
                        : "+f"(acc[mi][ni][0]), "+f"(acc[mi][ni][1]),
                          "+f"(acc[mi][ni][2]), "+f"(acc[mi][ni][3])
                        : "r"(af[mi][0]), "r"(af[mi][1]), "r"(af[mi][2]), "r"(af[mi][3]),
                          "r"(bf[ni][0]), "r"(bf[ni][1]));
                }
        }
    };

    const int KT = K / 64;
    issue(0); CP_COMMIT();
    issue(1); CP_COMMIT();
    for (int kt = 0; kt < KT; kt++) {
        CP_WAIT1();
        __syncthreads();
        if (kt + 2 < KT) issue(kt + 2);
        CP_COMMIT();
        compute(kt % GT_STAGES);
    }

    // epilogue
    #pragma unroll
    for (int mi = 0; mi < 2; mi++) {
        #pragma unroll
        for (int half = 0; half < 2; half++) {
            int r = m0 + wm * 32 + mi * 16 + (l >> 2) + half * 8;
            int cr = flipC ? fliprow(r) : r;
            const float* rp = resid + (size_t)cr * ldc + ccol;
            #pragma unroll
            for (int ni = 0; ni < 8; ni++) {
                int col = n0 + wn * 64 + ni * 8 + ((l & 3) << 1);
                if (col < N) {
                    float v0 = acc[mi][ni][half * 2 + 0];
                    float v1 = acc[mi][ni][half * 2 + 1];
                    if (bias)  { v0 += bias[col]; v1 += bias[col + 1]; }
                    if (resid) { v0 += rp[col];   v1 += rp[col + 1]; }
                    if (aux && col >= auxlo)
                        *(float2*)(aux + (size_t)cr * 16 + (col - auxlo)) =
                            make_float2(v0, v1);
                    if (halfOut) {
                        __half2* hp = (__half2*)((__half*)Cv + (size_t)cr * ldc + ccol + col);
                        *hp = __floats2half2_rn(v0, v1);
                    } else {
                        float* cp = (float*)Cv + (size_t)cr * ldc + ccol;
                        *(float2*)(cp + col) = make_float2(v0, v1);
                    }
                }
            }
        }
    }
}

// helper: silu
__device__ __forceinline__ float siluf(float v) { return v / (1.f + expf(-v)); }

// ======== fused conv + chunked scan pass A (local from zero) =====================
__global__ void __launch_bounds__(256)
scanA_kernel(const float* __restrict__ Al0, const float* __restrict__ Al1,
             const float* __restrict__ cw0, const float* __restrict__ cw1,
             const float* __restrict__ cb0, const float* __restrict__ cb1,
             const float* __restrict__ db0, const float* __restrict__ db1)
{
    const int c = blockIdx.x, h = blockIdx.y;
    const int b = blockIdx.z & (B_SZ - 1), dir = blockIdx.z >> 3;
    const int tid = threadIdx.x;
    const int p = tid >> 2, q = tid & 3;
    const float Aneg = -expf((dir ? Al1 : Al0)[h]);
    const float* conv_w  = dir ? cw1 : cw0;
    const float* conv_b  = dir ? cb1 : cb0;
    const float* dt_bias = dir ? db1 : db0;
    const __half* zx = g_zx16[dir];

    __shared__ float szx[CS + 3][80];
    __shared__ float sx[CS][64];
    __shared__ float sB[CS][16];
    __shared__ float sdt[CS];
    __shared__ float sdA[CS];
    __shared__ float scw[80 * 4];
    __shared__ float scb[80];

    const int l0 = c * CS;
    const size_t rowbase = (size_t)b * L_SEQ + l0;

    for (int idx = tid; idx < (CS + 3) * 80; idx += 256) {
        int s = idx / 80, ch = idx % 80;
        int ll = l0 + s - 3;
        int zc = (ch < 64) ? (D_INNER + h * 64 + ch) : (D_INNER + 1024 + (ch - 64));
        szx[s][ch] = (ll >= 0)
            ? __half2float(zx[((size_t)b * L_SEQ + ll) * D_IN_PROJ + zc]) : 0.f;
    }
    if (tid < 80) {
        int cc = (tid < 64) ? (h * 64 + tid) : (1024 + (tid - 64));
        scb[tid] = conv_b[cc];
        #pragma unroll
        for (int k = 0; k < 4; k++) scw[tid * 4 + k] = conv_w[cc * 4 + k];
    }
    if (tid < CS) {
        float raw = g_dtraw[dir][(rowbase + tid) * 16 + h] + dt_bias[h];
        float sp = (raw > 20.f) ? raw : log1pf(expf(raw));
        sdt[tid] = sp;
        sdA[tid] = expf(sp * Aneg);
    }
    __syncthreads();

    for (int idx = tid; idx < CS * 80; idx += 256) {
        int s = idx / 80, ch = idx % 80;
        float v = scb[ch];
        #pragma unroll
        for (int k = 0; k < 4; k++) v += szx[s + k][ch] * scw[ch * 4 + k];
        v = siluf(v);
        if (ch < 64) sx[s][ch] = v; else sB[s][ch - 64] = v;
    }
    __syncthreads();

    float h0 = 0.f, h1 = 0.f, h2 = 0.f, h3 = 0.f;
    #pragma unroll 4
    for (int s = 0; s < CS; s++) {
        float dA = sdA[s];
        float coef = sdt[s] * sx[s][p];
        float4 Bv = *(const float4*)&sB[s][q * 4];
        h0 = h0 * dA + coef * Bv.x;
        h1 = h1 * dA + coef * Bv.y;
        h2 = h2 * dA + coef * Bv.z;
        h3 = h3 * dA + coef * Bv.w;
    }
    size_t base = (((size_t)(b * NHEADS + h) * NC + c) << 10) + tid * 4;
    *(float4*)&g_hstate[dir][base] = make_float4(h0, h1, h2, h3);
    if (tid == 0) {
        float P = 1.f;
        for (int s = 0; s < CS; s++) P *= sdA[s];
        g_P[dir][(b * NHEADS + h) * NC + c] = P;
    }
}

// ======== chunked scan: middle combine ==========================================
__global__ void __launch_bounds__(256)
scanMid_kernel()
{
    const int h = blockIdx.x, b = blockIdx.y, dir = blockIdx.z;
    const int tid = threadIdx.x;
    float* hs = g_hstate[dir];
    const size_t base = ((size_t)(b * NHEADS + h) * NC << 10) + tid * 4;
    __shared__ float sP[NC];
    if (tid < NC) sP[tid] = g_P[dir][(b * NHEADS + h) * NC + tid];
    __syncthreads();
    float4 nxt = *(float4*)&hs[base];
    float4 run = make_float4(0.f, 0.f, 0.f, 0.f);
    for (int c = 0; c < NC; c++) {
        float4 endv = nxt;
        if (c + 1 < NC) nxt = *(float4*)&hs[base + ((size_t)(c + 1) << 10)];
        *(float4*)&hs[base + ((size_t)c << 10)] = run;
        float P = sP[c];
        run.x = P * run.x + endv.x;
        run.y = P * run.y + endv.y;
        run.z = P * run.z + endv.z;
        run.w = P * run.w + endv.w;
    }
}

// ======== fused conv + scan pass B + gate(silu(z)) + fp16 y16 + partial ssq =====
// dynamic smem (floats): szx 67*96 (reused as sy) | sx 4096 | sB 1024 | sC 1024 |
//   sdt 64 | sdA 64 | scw 384 | scb 96 | sz 4096
#define SB_SMEM ((67 * 96 + 4096 + 1024 + 1024 + 64 + 64 + 384 + 96 + 4096) * 4)

__global__ void __launch_bounds__(256)
scanB_kernel(const float* __restrict__ Al0, const float* __restrict__ Al1,
             const float* __restrict__ Dp0, const float* __restrict__ Dp1,
             const float* __restrict__ cw0, const float* __restrict__ cw1,
             const float* __restrict__ cb0, const float* __restrict__ cb1,
             const float* __restrict__ db0, const float* __restrict__ db1)
{
    extern __shared__ float sm[];
    float* szx = sm;                       // [67][96]
    float* sx  = sm + 67 * 96;             // [64][64]
    float* sB  = sx + 4096;                // [64][16]
    float* sC  = sB + 1024;                // [64][16]
    float* sdt = sC + 1024;                // [64]
    float* sdA = sdt + 64;                 // [64]
    float* scw = sdA + 64;                 // [96*4]
    float* scb = scw + 384;                // [96]
    float* sz  = scb + 96;                 // [64][64] gating z
    float* sy  = szx;                      // reuse after conv phase

    const int c = blockIdx.x, h = blockIdx.y;
    const int b = blockIdx.z & (B_SZ - 1), dir = blockIdx.z >> 3;
    const int tid = threadIdx.x;
    const int p = tid >> 2, q = tid & 3;
    const float Aneg = -expf((dir ? Al1 : Al0)[h]);
    const float Dh = (dir ? Dp1 : Dp0)[h];
    const float* conv_w  = dir ? cw1 : cw0;
    const float* conv_b  = dir ? cb1 : cb0;
    const float* dt_bias = dir ? db1 : db0;
    const __half* zx = g_zx16[dir];

    const int l0 = c * CS;
    const size_t rowbase = (size_t)b * L_SEQ + l0;

    for (int idx = tid; idx < (CS + 3) * 96; idx += 256) {
        int s = idx / 96, ch = idx % 96;
        int ll = l0 + s - 3;
        int zc = (ch < 64) ? (D_INNER + h * 64 + ch) : (D_INNER + 1024 + (ch - 64));
        szx[s * 96 + ch] = (ll >= 0)
            ? __half2float(zx[((size_t)b * L_SEQ + ll) * D_IN_PROJ + zc]) : 0.f;
    }
    // gating z slice: columns h*64..h*64+63 of zx (z block = first 1024 cols)
    for (int idx = tid; idx < CS * 64; idx += 256) {
        int s = idx >> 6, ch = idx & 63;
        sz[idx] = __half2float(zx[(rowbase + s) * D_IN_PROJ + h * 64 + ch]);
    }
    if (tid < 96) {
        int cc = (tid < 64) ? (h * 64 + tid) : (1024 + (tid - 64));
        scb[tid] = conv_b[cc];
        #pragma unroll
        for (int k = 0; k < 4; k++) scw[tid * 4 + k] = conv_w[cc * 4 + k];
    }
    if (tid < CS) {
        float raw = g_dtraw[dir][(rowbase + tid) * 16 + h] + dt_bias[h];
        float sp = (raw > 20.f) ? raw : log1pf(expf(raw));
        sdt[tid] = sp;
        sdA[tid] = expf(sp * Aneg);
    }
    float4 hin = *(float4*)&g_hstate[dir][(((size_t)(b * NHEADS + h) * NC + c) << 10) + tid * 4];
    __syncthreads();

    for (int idx = tid; idx < CS * 96; idx += 256) {
        int s = idx / 96, ch = idx % 96;
        float v = scb[ch];
        #pragma unroll
        for (int k = 0; k < 4; k++) v += szx[(s + k) * 96 + ch] * scw[ch * 4 + k];
        v = siluf(v);
        if (ch < 64) sx[s * 64 + ch] = v;
        else if (ch < 80) sB[s * 16 + (ch - 64)] = v;
        else sC[s * 16 + (ch - 80)] = v;
    }
    __syncthreads();

    float h0 = hin.x, h1 = hin.y, h2 = hin.z, h3 = hin.w;
    for (int s = 0; s < CS; s++) {
        float dA = sdA[s];
        float xv = sx[s * 64 + p];
        float coef = sdt[s] * xv;
        float4 Bv = *(const float4*)&sB[s * 16 + q * 4];
        float4 Cv = *(const float4*)&sC[s * 16 + q * 4];
        h0 = h0 * dA + coef * Bv.x;
        h1 = h1 * dA + coef * Bv.y;
        h2 = h2 * dA + coef * Bv.z;
        h3 = h3 * dA + coef * Bv.w;
        float yp = h0 * Cv.x + h1 * Cv.y + h2 * Cv.z + h3 * Cv.w;
        yp += __shfl_xor_sync(0xffffffffu, yp, 1);
        yp += __shfl_xor_sync(0xffffffffu, yp, 2);
        if (q == 0) sy[s * 64 + p] = yp + Dh * xv;
    }
    __syncthreads();

    // gate + fp16 write + per-row partial ssq (one warp per row: s = 8j + warp)
    const int lane = tid & 31;
    #pragma unroll 1
    for (int j = 0; j < 8; j++) {
        int idx2 = tid + j * 256;          // half2 index
        int s = idx2 >> 5;                 // row within chunk
        int pp = (idx2 & 31) * 2;
        float g0 = sy[s * 64 + pp]     * siluf(sz[s * 64 + pp]);
        float g1 = sy[s * 64 + pp + 1] * siluf(sz[s * 64 + pp + 1]);
        *(__half2*)&g_y16[dir][(rowbase + s) * D_INNER + h * 64 + pp] =
            __floats2half2_rn(g0, g1);
        float ss = g0 * g0 + g1 * g1;
        #pragma unroll
        for (int o = 16; o > 0; o >>= 1) ss += __shfl_xor_sync(0xffffffffu, ss, o);
        if (lane == 0) g_ssq[dir][(rowbase + s) * NHEADS + h] = ss;
    }
}

// ------- RMS scale: y16 *= rsqrt(mean(ssq)) * norm_w (in place) ------------------
__global__ void rms_scale_kernel(const float* __restrict__ nw0, const float* __restrict__ nw1)
{
    const int row = blockIdx.x, dir = blockIdx.y, tid = threadIdx.x;  // 256 thr
    __shared__ float sp[16];
    __shared__ float ssc;
    if (tid < 16) sp[tid] = g_ssq[dir][(size_t)row * NHEADS + tid];
    __syncthreads();
    if (tid == 0) {
        float t = 0.f;
        #pragma unroll
        for (int i = 0; i < 16; i++) t += sp[i];
        ssc = rsqrtf(t * (1.f / D_INNER) + 1e-5f);
    }
    __syncthreads();
    const float sc = ssc;
    const float* nw = dir ? nw1 : nw0;
    float4 nv = *(const float4*)&nw[tid * 4];
    __half2* yp = (__half2*)&g_y16[dir][(size_t)row * D_INNER + tid * 4];
    float2 fa = __half22float2(yp[0]);
    float2 fb = __half22float2(yp[1]);
    yp[0] = __floats2half2_rn(fa.x * sc * nv.x, fa.y * sc * nv.y);
    yp[1] = __floats2half2_rn(fb.x * sc * nv.z, fb.y * sc * nv.w);
}

// ---------------- final LayerNorm over 512 -> d_out ------------------------------
__global__ void ln_kernel(const float* __restrict__ ln_w, const float* __restrict__ ln_b,
                          float* __restrict__ out)
{
    const int row = blockIdx.x, tid = threadIdx.x;  // 128 threads
    const size_t base = (size_t)row * D_MODEL;
    float4 v = *(const float4*)&g_pre[base + tid * 4];
    float s = v.x + v.y + v.z + v.w;
    float s2 = v.x * v.x + v.y * v.y + v.z * v.z + v.w * v.w;
    __shared__ float rs[4], rs2[4];
    #pragma unroll
    for (int o = 16; o > 0; o >>= 1) {
        s  += __shfl_xor_sync(0xffffffffu, s, o);
        s2 += __shfl_xor_sync(0xffffffffu, s2, o);
    }
    if ((tid & 31) == 0) { rs[tid >> 5] = s; rs2[tid >> 5] = s2; }
    __syncthreads();
    float ts = rs[0] + rs[1] + rs[2] + rs[3];
    float ts2 = rs2[0] + rs2[1] + rs2[2] + rs2[3];
    float mu = ts * (1.f / D_MODEL);
    float var = ts2 * (1.f / D_MODEL) - mu * mu;
    float isd = rsqrtf(var + 1e-5f);
    float4 wv = *(const float4*)&ln_w[tid * 4];
    float4 bv = *(const float4*)&ln_b[tid * 4];
    float4 o;
    o.x = (v.x - mu) * isd * wv.x + bv.x;
    o.y = (v.y - mu) * isd * wv.y + bv.y;
    o.z = (v.z - mu) * isd * wv.z + bv.z;
    o.w = (v.w - mu) * isd * wv.w + bv.w;
    *(float4*)&out[base + tid * 4] = o;
}

// ---------------- orchestration ---------------------------------------------------
extern "C" void kernel_launch(void* const* d_in, const int* in_sizes, int n_in,
                              void* d_out, int out_size)
{
    const float* x      = (const float*)d_in[0];
    const float* f_in_proj  = (const float*)d_in[1];
    const float* f_conv_w   = (const float*)d_in[2];
    const float* f_conv_b   = (const float*)d_in[3];
    const float* f_dt_bias  = (const float*)d_in[4];
    const float* f_A_log    = (const float*)d_in[5];
    const float* f_D        = (const float*)d_in[6];
    const float* f_norm_w   = (const float*)d_in[7];
    const float* f_out_proj = (const float*)d_in[8];
    const float* b_in_proj  = (const float*)d_in[9];
    const float* b_conv_w   = (const float*)d_in[10];
    const float* b_conv_b   = (const float*)d_in[11];
    const float* b_dt_bias  = (const float*)d_in[12];
    const float* b_A_log    = (const float*)d_in[13];
    const float* b_D        = (const float*)d_in[14];
    const float* b_norm_w   = (const float*)d_in[15];
    const float* b_out_proj = (const float*)d_in[16];
    const float* proj_w = (const float*)d_in[17];
    const float* proj_b = (const float*)d_in[18];
    const float* ln_w   = (const float*)d_in[19];
    const float* ln_b   = (const float*)d_in[20];

    float *pre, *dtraw;
    __half *zx16, *x16, *wip16, *wpr16, *wofT16, *wcomb16, *y16;
    cudaGetSymbolAddress((void**)&zx16, g_zx16);
    cudaGetSymbolAddress((void**)&dtraw, g_dtraw);
    cudaGetSymbolAddress((void**)&pre, g_pre);
    cudaGetSymbolAddress((void**)&x16, g_x16);
    cudaGetSymbolAddress((void**)&wip16, g_wip16);
    cudaGetSymbolAddress((void**)&wpr16, g_wpr16);
    cudaGetSymbolAddress((void**)&wofT16, g_wofT16);
    cudaGetSymbolAddress((void**)&wcomb16, g_wcomb16);
    cudaGetSymbolAddress((void**)&y16, g_y16);

    cudaFuncSetAttribute(gemm_f16, cudaFuncAttributeMaxDynamicSharedMemorySize, GT_SMEM);
    cudaFuncSetAttribute(scanB_kernel, cudaFuncAttributeMaxDynamicSharedMemorySize, SB_SMEM);

    // fp32 -> fp16 conversions + out_proj transposes
    f2h_kernel<<<2048, 256>>>(x, x16, BL * D_MODEL / 4);
    f2h_kernel<<<256, 256>>>(f_in_proj, wip16, D_IN_PROJ * D_MODEL / 4);
    f2h_kernel<<<256, 256>>>(b_in_proj, wip16 + (size_t)D_IN_PROJ * D_MODEL,
                             D_IN_PROJ * D_MODEL / 4);
    f2h_kernel<<<128, 256>>>(proj_w, wpr16, D_MODEL * D_INNER / 4);
    tr_f2h_kernel<<<dim3(32, 16, 2), dim3(32, 8)>>>(
        f_out_proj, b_out_proj, wofT16, wofT16 + (size_t)D_INNER * D_MODEL);

    // weight combine: wcomb[m][k + dir*1024] = proj_w[m][n + dir*512] * out_proj_dir[n][k]
    gemm_f16<<<dim3(D_INNER / 128, D_MODEL / 128, 2), 256, GT_SMEM>>>(
        wpr16, wpr16 + 512, D_INNER,
        wofT16, wofT16 + (size_t)D_INNER * D_MODEL, D_MODEL,
        wcomb16, wcomb16, 2 * D_INNER, D_INNER,
        D_INNER, D_MODEL, D_MODEL, 0, 0, 1, nullptr, nullptr, nullptr, 0);

    // in_proj both dirs -> fp16 zx + fp32 dt aux
    gemm_f16<<<dim3((D_IN_PROJ + 127) / 128, BL / 128, 2), 256, GT_SMEM>>>(
        x16, x16, D_MODEL, wip16, wip16 + (size_t)D_IN_PROJ * D_MODEL, D_MODEL,
        zx16, zx16 + (size_t)BL * D_IN_PROJ, D_IN_PROJ, 0,
        D_IN_PROJ, D_MODEL, D_MODEL, 0b10, 0, 1, nullptr, nullptr,
        dtraw, D_INNER + CONV_DIM);

    // fused conv + scan (+ gate + fp16 y emit in pass B)
    scanA_kernel<<<dim3(NC, NHEADS, 2 * B_SZ), 256>>>(
        f_A_log, b_A_log, f_conv_w, b_conv_w, f_conv_b, b_conv_b, f_dt_bias, b_dt_bias);
    scanMid_kernel<<<dim3(NHEADS, B_SZ, 2), 256>>>();
    scanB_kernel<<<dim3(NC, NHEADS, 2 * B_SZ), 256, SB_SMEM>>>(
        f_A_log, b_A_log, f_D, b_D,
        f_conv_w, b_conv_w, f_conv_b, b_conv_b, f_dt_bias, b_dt_bias);

    // RMS normalization scale (in place on y16)
    rms_scale_kernel<<<dim3(BL, 2), 256>>>(f_norm_w, b_norm_w);

    // combined projection: pre = x + proj_b + [y_f | y_b(flip)] @ wcomb^T  (K=2048)
    gemm_f16<<<dim3(D_MODEL / 128, BL / 128, 1), 256, GT_SMEM>>>(
        y16, y16 + (size_t)BL * D_INNER, D_INNER,
        wcomb16, wcomb16, 2 * D_INNER,
        pre, pre, D_MODEL, 0,
        D_MODEL, 2 * D_INNER, D_INNER, 0b10, 0, 0, proj_b, x,
        nullptr, 0);

    ln_kernel<<<BL, 128>>>(ln_w, ln_b, (float*)d_out);
}

// round 12
// speedup vs baseline: 1.2377x; 1.2377x over previous
#include <cuda_runtime.h>
#include <cuda_fp16.h>
#include <cstdint>

#define B_SZ    8
#define L_SEQ   4096
#define D_MODEL 512
#define D_INNER 1024
#define NHEADS  16
#define HEADDIM 64
#define D_STATE 16
#define CONV_DIM 1056
#define D_IN_PROJ 2096
#define BL      (B_SZ * L_SEQ)
#define CS      64
#define NC      (L_SEQ / CS)
#define AUXZ    ((size_t)BL * 16)

// ---------------- scratch (device globals; no allocation allowed) ----------------
__device__ __half g_zx16[2][(size_t)BL * D_IN_PROJ];   // in_proj out (fp16)
__device__ float g_dtraw[2][(size_t)BL * 16];          // dt pre-softplus (fp32)
__device__ float g_pre[(size_t)BL * D_MODEL];
__device__ float g_hstate[2][(size_t)B_SZ * NHEADS * NC * 1024];
__device__ float g_P[2][B_SZ * NHEADS * NC];

__device__ __half g_x16[(size_t)BL * D_MODEL];
__device__ __half g_wip16[2][(size_t)D_IN_PROJ * D_MODEL];
__device__ __half g_wpr16[(size_t)D_MODEL * D_INNER];
__device__ __half g_wofT16[2][(size_t)D_INNER * D_MODEL]; // out_proj^T fp16
__device__ __half g_wcomb16[(size_t)D_MODEL * 2 * D_INNER]; // [512][2048]
__device__ __half g_y16[2][(size_t)BL * D_INNER];      // y (pre-gate) -> gated/normed

__device__ __forceinline__ int fliprow(int r) {
    return (r & ~(L_SEQ - 1)) | ((L_SEQ - 1) - (r & (L_SEQ - 1)));
}
__device__ __forceinline__ void cpa16(uint32_t dst, const void* src, int sz) {
    asm volatile("cp.async.cg.shared.global [%0], [%1], 16, %2;"
                 :: "r"(dst), "l"(src), "r"(sz));
}
#define CP_COMMIT() asm volatile("cp.async.commit_group;" ::: "memory")
#define CP_WAIT1()  asm volatile("cp.async.wait_group 1;" ::: "memory")

// ---------------- fp32 -> fp16 convert (grid-stride, float4) ---------------------
__global__ void f2h_kernel(const float* __restrict__ src, __half* __restrict__ dst, int n4)
{
    for (int i = blockIdx.x * blockDim.x + threadIdx.x; i < n4; i += gridDim.x * blockDim.x) {
        float4 v = *(const float4*)(src + (size_t)i * 4);
        __half2* d = (__half2*)(dst + (size_t)i * 4);
        d[0] = __floats2half2_rn(v.x, v.y);
        d[1] = __floats2half2_rn(v.z, v.w);
    }
}

// ------------- transpose fp32 [512][1024] -> fp16 [1024][512] --------------------
__global__ void tr_f2h_kernel(const float* __restrict__ s0, const float* __restrict__ s1,
                              __half* __restrict__ d0, __half* __restrict__ d1)
{
    const float* src = blockIdx.z ? s1 : s0;
    __half* dst = blockIdx.z ? d1 : d0;
    __shared__ float t[32][33];
    int c0 = blockIdx.x * 32, r0 = blockIdx.y * 32;
    int tx = threadIdx.x, ty = threadIdx.y;   // 32 x 8
    #pragma unroll
    for (int i = 0; i < 4; i++)
        t[ty + i * 8][tx] = src[(size_t)(r0 + ty + i * 8) * D_INNER + c0 + tx];
    __syncthreads();
    #pragma unroll
    for (int i = 0; i < 4; i++)
        dst[(size_t)(c0 + ty + i * 8) * D_MODEL + r0 + tx] =
            __float2half_rn(t[tx][ty + i * 8]);
}

// ============ fp16 mma.sync GEMM: C = A[M,K] @ W[N,K]^T (+bias +resid) ==========
// CTA tile 128x128, BK=64, 3-stage cp.async, 8 warps (4m x 2n), warp tile 32x64.
// grid.z selects direction set; ksplit<K enables dual-A k-stitching.
#define GT_STAGES 3
#define GT_ASZ 16384
#define GT_STG (2 * GT_ASZ)
#define GT_SMEM (GT_STAGES * GT_STG + 1024)

__global__ void __launch_bounds__(256, 2)
gemm_f16(const __half* __restrict__ A0, const __half* __restrict__ A1, int lda,
         const __half* __restrict__ W0, const __half* __restrict__ W1, int Wld,
         void* C0v, void* C1v, int ldc, int ccolstep,
         int N, int K, int ksplit,
         int flipAmask, int flipCmask, int halfOut,
         const float* __restrict__ bias,
         const float* __restrict__ resid,
         float* __restrict__ aux, int auxlo)
{
    extern __shared__ char dsm[];
    const uint32_t sb_raw = (uint32_t)__cvta_generic_to_shared(dsm);
    const uint32_t sb = (sb_raw + 1023u) & ~1023u;

    const int z = blockIdx.z;
    const int dual = (ksplit < K);
    const __half* Aa = dual ? A0 : (z ? A1 : A0);
    const __half* W = z ? W1 : W0;
    void* Cv = z ? C1v : C0v;
    const int ccol = z * ccolstep;
    const int flip_a = dual ? (flipAmask & 1) : ((flipAmask >> z) & 1);
    const int flip_b = (flipAmask >> 1) & 1;
    const int flipC = (flipCmask >> z) & 1;
    if (aux) aux += (size_t)z * AUXZ;

    const int tid = threadIdx.x;
    const int l   = tid & 31;
    const int w   = tid >> 5;
    const int wm  = w >> 1;
    const int wn  = w & 1;
    const int m0  = blockIdx.y * 128;
    const int n0  = blockIdx.x * 128;

    const int lr = l & 15;
    const int lc = l >> 4;
    const int lx = lr & 7;

    int arowA[4], arowB[4];
    #pragma unroll
    for (int i = 0; i < 4; i++) {
        int rr = (tid + i * 256) >> 3;
        int r = m0 + rr;
        arowA[i] = flip_a ? fliprow(r) : r;
        arowB[i] = flip_b ? fliprow(r) : r;
    }

    float acc[2][8][4];
    #pragma unroll
    for (int mi = 0; mi < 2; mi++)
        #pragma unroll
        for (int ni = 0; ni < 8; ni++)
            #pragma unroll
            for (int k = 0; k < 4; k++) acc[mi][ni][k] = 0.f;

    auto issue = [&](int s) {
        const int k0 = s * 64;
        const uint32_t base = sb + (s % GT_STAGES) * GT_STG;
        const __half* Ap = Aa;
        const int* ar = arowA;
        int kk = k0;
        if (dual && k0 >= ksplit) { Ap = A1; ar = arowB; kk = k0 - ksplit; }
        #pragma unroll
        for (int i = 0; i < 4; i++) {
            int q = tid + i * 256;
            int rr = q >> 3, ch = q & 7;
            int off = rr * 128 + ((ch ^ (rr & 7)) << 4);
            cpa16(base + off, Ap + (size_t)ar[i] * lda + kk + ch * 8, 16);
        }
        #pragma unroll
        for (int i = 0; i < 4; i++) {
            int q = tid + i * 256;
            int rr = q >> 3, ch = q & 7;
            int off = rr * 128 + ((ch ^ (rr & 7)) << 4);
            int n = n0 + rr;
            cpa16(base + GT_ASZ + off,
                  W + (size_t)(n < N ? n : 0) * Wld + k0 + ch * 8, (n < N) ? 16 : 0);
        }
    };
    auto compute = [&](int s) {
        const uint32_t Ab = sb + s * GT_STG;
        const uint32_t Bb = Ab + GT_ASZ;
        #pragma unroll
        for (int ks = 0; ks < 4; ks++) {
            const int chsel = ((ks << 1) | lc) ^ lx;
            uint32_t af[2][4];
            #pragma unroll
            for (int mi = 0; mi < 2; mi++) {
                uint32_t ad = Ab + (wm * 32 + mi * 16 + lr) * 128 + (chsel << 4);
                asm volatile("ldmatrix.sync.aligned.m8n8.x4.shared.b16 {%0,%1,%2,%3}, [%4];"
                    : "=r"(af[mi][0]), "=r"(af[mi][1]), "=r"(af[mi][2]), "=r"(af[mi][3])
                    : "r"(ad));
            }
            uint32_t bf[8][2];
            #pragma unroll
            for (int p = 0; p < 4; p++) {
                uint32_t bd = Bb + (wn * 64 + p * 16 + lr) * 128 + (chsel << 4);
                uint32_t q0, q1, q2, q3;
                asm volatile("ldmatrix.sync.aligned.m8n8.x4.shared.b16 {%0,%1,%2,%3}, [%4];"
                    : "=r"(q0), "=r"(q1), "=r"(q2), "=r"(q3) : "r"(bd));
                bf[2 * p][0] = q0;     bf[2 * p][1] = q2;
                bf[2 * p + 1][0] = q1; bf[2 * p + 1][1] = q3;
            }
            #pragma unroll
            for (int mi = 0; mi < 2; mi++)
                #pragma unroll
                for (int ni = 0; ni < 8; ni++) {
                    asm volatile(
                        "mma.sync.aligned.m16n8k16.row.col.f32.f16.f16.f32 "
                        "{%0,%1,%2,%3},{%4,%5,%6,%7},{%8,%9},{%0,%1,%2,%3};"
                        : "+f"(acc[mi][ni][0]), "+f"(acc[mi][ni][1]),
                          "+f"(acc[mi][ni][2]), "+f"(acc[mi][ni][3])
                        : "r"(af[mi][0]), "r"(af[mi][1]), "r"(af[mi][2]), "r"(af[mi][3]),
                          "r"(bf[ni][0]), "r"(bf[ni][1]));
                }
        }
    };

    const int KT = K / 64;
    issue(0); CP_COMMIT();
    issue(1); CP_COMMIT();
    for (int kt = 0; kt < KT; kt++) {
        CP_WAIT1();
        __syncthreads();
        if (kt + 2 < KT) issue(kt + 2);
        CP_COMMIT();
        compute(kt % GT_STAGES);
    }

    // epilogue
    #pragma unroll
    for (int mi = 0; mi < 2; mi++) {
        #pragma unroll
        for (int half = 0; half < 2; half++) {
            int r = m0 + wm * 32 + mi * 16 + (l >> 2) + half * 8;
            int cr = flipC ? fliprow(r) : r;
            const float* rp = resid + (size_t)cr * ldc + ccol;
            #pragma unroll
            for (int ni = 0; ni < 8; ni++) {
                int col = n0 + wn * 64 + ni * 8 + ((l & 3) << 1);
                if (col < N) {
                    float v0 = acc[mi][ni][half * 2 + 0];
                    float v1 = acc[mi][ni][half * 2 + 1];
                    if (bias)  { v0 += bias[col]; v1 += bias[col + 1]; }
                    if (resid) { v0 += rp[col];   v1 += rp[col + 1]; }
                    if (aux && col >= auxlo)
                        *(float2*)(aux + (size_t)cr * 16 + (col - auxlo)) =
                            make_float2(v0, v1);
                    if (halfOut) {
                        __half2* hp = (__half2*)((__half*)Cv + (size_t)cr * ldc + ccol + col);
                        *hp = __floats2half2_rn(v0, v1);
                    } else {
                        float* cp = (float*)Cv + (size_t)cr * ldc + ccol;
                        *(float2*)(cp + col) = make_float2(v0, v1);
                    }
                }
            }
        }
    }
}

// helper: silu
__device__ __forceinline__ float siluf(float v) { return v / (1.f + expf(-v)); }

// ======== fused conv + chunked scan pass A (local from zero) =====================
__global__ void __launch_bounds__(256)
scanA_kernel(const float* __restrict__ Al0, const float* __restrict__ Al1,
             const float* __restrict__ cw0, const float* __restrict__ cw1,
             const float* __restrict__ cb0, const float* __restrict__ cb1,
             const float* __restrict__ db0, const float* __restrict__ db1)
{
    const int c = blockIdx.x, h = blockIdx.y;
    const int b = blockIdx.z & (B_SZ - 1), dir = blockIdx.z >> 3;
    const int tid = threadIdx.x;
    const int p = tid >> 2, q = tid & 3;
    const float Aneg = -expf((dir ? Al1 : Al0)[h]);
    const float* conv_w  = dir ? cw1 : cw0;
    const float* conv_b  = dir ? cb1 : cb0;
    const float* dt_bias = dir ? db1 : db0;
    const __half* zx = g_zx16[dir];

    __shared__ float szx[CS + 3][80];
    __shared__ float sx[CS][64];
    __shared__ float sB[CS][16];
    __shared__ float sdt[CS];
    __shared__ float sdA[CS];
    __shared__ float scw[80 * 4];
    __shared__ float scb[80];

    const int l0 = c * CS;
    const size_t rowbase = (size_t)b * L_SEQ + l0;

    for (int idx = tid; idx < (CS + 3) * 80; idx += 256) {
        int s = idx / 80, ch = idx % 80;
        int ll = l0 + s - 3;
        int zc = (ch < 64) ? (D_INNER + h * 64 + ch) : (D_INNER + 1024 + (ch - 64));
        szx[s][ch] = (ll >= 0)
            ? __half2float(zx[((size_t)b * L_SEQ + ll) * D_IN_PROJ + zc]) : 0.f;
    }
    if (tid < 80) {
        int cc = (tid < 64) ? (h * 64 + tid) : (1024 + (tid - 64));
        scb[tid] = conv_b[cc];
        #pragma unroll
        for (int k = 0; k < 4; k++) scw[tid * 4 + k] = conv_w[cc * 4 + k];
    }
    if (tid < CS) {
        float raw = g_dtraw[dir][(rowbase + tid) * 16 + h] + dt_bias[h];
        float sp = (raw > 20.f) ? raw : log1pf(expf(raw));
        sdt[tid] = sp;
        sdA[tid] = expf(sp * Aneg);
    }
    __syncthreads();

    for (int idx = tid; idx < CS * 80; idx += 256) {
        int s = idx / 80, ch = idx % 80;
        float v = scb[ch];
        #pragma unroll
        for (int k = 0; k < 4; k++) v += szx[s + k][ch] * scw[ch * 4 + k];
        v = siluf(v);
        if (ch < 64) sx[s][ch] = v; else sB[s][ch - 64] = v;
    }
    __syncthreads();

    float h0 = 0.f, h1 = 0.f, h2 = 0.f, h3 = 0.f;
    #pragma unroll 4
    for (int s = 0; s < CS; s++) {
        float dA = sdA[s];
        float coef = sdt[s] * sx[s][p];
        float4 Bv = *(const float4*)&sB[s][q * 4];
        h0 = h0 * dA + coef * Bv.x;
        h1 = h1 * dA + coef * Bv.y;
        h2 = h2 * dA + coef * Bv.z;
        h3 = h3 * dA + coef * Bv.w;
    }
    size_t base = (((size_t)(b * NHEADS + h) * NC + c) << 10) + tid * 4;
    *(float4*)&g_hstate[dir][base] = make_float4(h0, h1, h2, h3);
    if (tid == 0) {
        float P = 1.f;
        for (int s = 0; s < CS; s++) P *= sdA[s];
        g_P[dir][(b * NHEADS + h) * NC + c] = P;
    }
}

// ======== chunked scan: middle combine ==========================================
__global__ void __launch_bounds__(256)
scanMid_kernel()
{
    const int h = blockIdx.x, b = blockIdx.y, dir = blockIdx.z;
    const int tid = threadIdx.x;
    float* hs = g_hstate[dir];
    const size_t base = ((size_t)(b * NHEADS + h) * NC << 10) + tid * 4;
    __shared__ float sP[NC];
    if (tid < NC) sP[tid] = g_P[dir][(b * NHEADS + h) * NC + tid];
    __syncthreads();
    float4 nxt = *(float4*)&hs[base];
    float4 run = make_float4(0.f, 0.f, 0.f, 0.f);
    for (int c = 0; c < NC; c++) {
        float4 endv = nxt;
        if (c + 1 < NC) nxt = *(float4*)&hs[base + ((size_t)(c + 1) << 10)];
        *(float4*)&hs[base + ((size_t)c << 10)] = run;
        float P = sP[c];
        run.x = P * run.x + endv.x;
        run.y = P * run.y + endv.y;
        run.z = P * run.z + endv.z;
        run.w = P * run.w + endv.w;
    }
}

// ======== fused conv + chunked scan pass B (seeded, emit y fp16) =================
#define SB_SMEM ((67 * 96 + 64 * 64 + 1024 + 1024 + 64 + 64 + 384 + 96) * 4)

__global__ void __launch_bounds__(256)
scanB_kernel(const float* __restrict__ Al0, const float* __restrict__ Al1,
             const float* __restrict__ Dp0, const float* __restrict__ Dp1,
             const float* __restrict__ cw0, const float* __restrict__ cw1,
             const float* __restrict__ cb0, const float* __restrict__ cb1,
             const float* __restrict__ db0, const float* __restrict__ db1)
{
    extern __shared__ float sm[];
    float* szx = sm;                       // [67][96]
    float* sx  = sm + 67 * 96;             // [64][64]
    float* sB  = sx + 4096;                // [64][16]
    float* sC  = sB + 1024;                // [64][16]
    float* sdt = sC + 1024;                // [64]
    float* sdA = sdt + 64;                 // [64]
    float* scw = sdA + 64;                 // [96*4]
    float* scb = scw + 384;                // [96]
    float* sy  = szx;                      // reuse after conv phase

    const int c = blockIdx.x, h = blockIdx.y;
    const int b = blockIdx.z & (B_SZ - 1), dir = blockIdx.z >> 3;
    const int tid = threadIdx.x;
    const int p = tid >> 2, q = tid & 3;
    const float Aneg = -expf((dir ? Al1 : Al0)[h]);
    const float Dh = (dir ? Dp1 : Dp0)[h];
    const float* conv_w  = dir ? cw1 : cw0;
    const float* conv_b  = dir ? cb1 : cb0;
    const float* dt_bias = dir ? db1 : db0;
    const __half* zx = g_zx16[dir];

    const int l0 = c * CS;
    const size_t rowbase = (size_t)b * L_SEQ + l0;

    for (int idx = tid; idx < (CS + 3) * 96; idx += 256) {
        int s = idx / 96, ch = idx % 96;
        int ll = l0 + s - 3;
        int zc = (ch < 64) ? (D_INNER + h * 64 + ch) : (D_INNER + 1024 + (ch - 64));
        szx[s * 96 + ch] = (ll >= 0)
            ? __half2float(zx[((size_t)b * L_SEQ + ll) * D_IN_PROJ + zc]) : 0.f;
    }
    if (tid < 96) {
        int cc = (tid < 64) ? (h * 64 + tid) : (1024 + (tid - 64));
        scb[tid] = conv_b[cc];
        #pragma unroll
        for (int k = 0; k < 4; k++) scw[tid * 4 + k] = conv_w[cc * 4 + k];
    }
    if (tid < CS) {
        float raw = g_dtraw[dir][(rowbase + tid) * 16 + h] + dt_bias[h];
        float sp = (raw > 20.f) ? raw : log1pf(expf(raw));
        sdt[tid] = sp;
        sdA[tid] = expf(sp * Aneg);
    }
    float4 hin = *(float4*)&g_hstate[dir][(((size_t)(b * NHEADS + h) * NC + c) << 10) + tid * 4];
    __syncthreads();

    for (int idx = tid; idx < CS * 96; idx += 256) {
        int s = idx / 96, ch = idx % 96;
        float v = scb[ch];
        #pragma unroll
        for (int k = 0; k < 4; k++) v += szx[(s + k) * 96 + ch] * scw[ch * 4 + k];
        v = siluf(v);
        if (ch < 64) sx[s * 64 + ch] = v;
        else if (ch < 80) sB[s * 16 + (ch - 64)] = v;
        else sC[s * 16 + (ch - 80)] = v;
    }
    __syncthreads();

    float h0 = hin.x, h1 = hin.y, h2 = hin.z, h3 = hin.w;
    for (int s = 0; s < CS; s++) {
        float dA = sdA[s];
        float xv = sx[s * 64 + p];
        float coef = sdt[s] * xv;
        float4 Bv = *(const float4*)&sB[s * 16 + q * 4];
        float4 Cv = *(const float4*)&sC[s * 16 + q * 4];
        h0 = h0 * dA + coef * Bv.x;
        h1 = h1 * dA + coef * Bv.y;
        h2 = h2 * dA + coef * Bv.z;
        h3 = h3 * dA + coef * Bv.w;
        float yp = h0 * Cv.x + h1 * Cv.y + h2 * Cv.z + h3 * Cv.w;
        yp += __shfl_xor_sync(0xffffffffu, yp, 1);
        yp += __shfl_xor_sync(0xffffffffu, yp, 2);
        if (q == 0) sy[s * 64 + p] = yp + Dh * xv;
    }
    __syncthreads();
    // emit y as fp16 (pre-gating)
    for (int idx = tid; idx < CS * 32; idx += 256) {
        int s = idx >> 5, pp = (idx & 31) * 2;
        *(__half2*)&g_y16[dir][(rowbase + s) * D_INNER + h * 64 + pp] =
            __floats2half2_rn(sy[s * 64 + pp], sy[s * 64 + pp + 1]);
    }
}

// ------- y16 *= silu(z); RMSNorm * norm_w (in place on y16) ----------------------
__global__ void gate_rms_kernel(const float* __restrict__ nw0, const float* __restrict__ nw1)
{
    const int row = blockIdx.x, dir = blockIdx.y, tid = threadIdx.x;
    const float* norm_w = dir ? nw1 : nw0;
    __half2* yp = (__half2*)&g_y16[dir][(size_t)row * D_INNER + tid * 4];
    const __half2* zp = (const __half2*)&g_zx16[dir][(size_t)row * D_IN_PROJ + tid * 4];
    float2 y01 = __half22float2(yp[0]);
    float2 y23 = __half22float2(yp[1]);
    float2 z01 = __half22float2(zp[0]);
    float2 z23 = __half22float2(zp[1]);
    float4 yv;
    yv.x = y01.x * siluf(z01.x);
    yv.y = y01.y * siluf(z01.y);
    yv.z = y23.x * siluf(z23.x);
    yv.w = y23.y * siluf(z23.y);
    float ss = yv.x * yv.x + yv.y * yv.y + yv.z * yv.z + yv.w * yv.w;
    __shared__ float red[8];
    #pragma unroll
    for (int o = 16; o > 0; o >>= 1) ss += __shfl_xor_sync(0xffffffffu, ss, o);
    if ((tid & 31) == 0) red[tid >> 5] = ss;
    __syncthreads();
    float tot = red[0] + red[1] + red[2] + red[3] + red[4] + red[5] + red[6] + red[7];
    float sc = rsqrtf(tot * (1.f / D_INNER) + 1e-5f);
    float4 nv = *(const float4*)&norm_w[tid * 4];
    yp[0] = __floats2half2_rn(yv.x * sc * nv.x, yv.y * sc * nv.y);
    yp[1] = __floats2half2_rn(yv.z * sc * nv.z, yv.w * sc * nv.w);
}

// ---------------- final LayerNorm over 512 -> d_out ------------------------------
__global__ void ln_kernel(const float* __restrict__ ln_w, const float* __restrict__ ln_b,
                          float* __restrict__ out)
{
    const int row = blockIdx.x, tid = threadIdx.x;  // 128 threads
    const size_t base = (size_t)row * D_MODEL;
    float4 v = *(const float4*)&g_pre[base + tid * 4];
    float s = v.x + v.y + v.z + v.w;
    float s2 = v.x * v.x + v.y * v.y + v.z * v.z + v.w * v.w;
    __shared__ float rs[4], rs2[4];
    #pragma unroll
    for (int o = 16; o > 0; o >>= 1) {
        s  += __shfl_xor_sync(0xffffffffu, s, o);
        s2 += __shfl_xor_sync(0xffffffffu, s2, o);
    }
    if ((tid & 31) == 0) { rs[tid >> 5] = s; rs2[tid >> 5] = s2; }
    __syncthreads();
    float ts = rs[0] + rs[1] + rs[2] + rs[3];
    float ts2 = rs2[0] + rs2[1] + rs2[2] + rs2[3];
    float mu = ts * (1.f / D_MODEL);
    float var = ts2 * (1.f / D_MODEL) - mu * mu;
    float isd = rsqrtf(var + 1e-5f);
    float4 wv = *(const float4*)&ln_w[tid * 4];
    float4 bv = *(const float4*)&ln_b[tid * 4];
    float4 o;
    o.x = (v.x - mu) * isd * wv.x + bv.x;
    o.y = (v.y - mu) * isd * wv.y + bv.y;
    o.z = (v.z - mu) * isd * wv.z + bv.z;
    o.w = (v.w - mu) * isd * wv.w + bv.w;
    *(float4*)&out[base + tid * 4] = o;
}

// ---------------- orchestration ---------------------------------------------------
extern "C" void kernel_launch(void* const* d_in, const int* in_sizes, int n_in,
                              void* d_out, int out_size)
{
    const float* x      = (const float*)d_in[0];
    const float* f_in_proj  = (const float*)d_in[1];
    const float* f_conv_w   = (const float*)d_in[2];
    const float* f_conv_b   = (const float*)d_in[3];
    const float* f_dt_bias  = (const float*)d_in[4];
    const float* f_A_log    = (const float*)d_in[5];
    const float* f_D        = (const float*)d_in[6];
    const float* f_norm_w   = (const float*)d_in[7];
    const float* f_out_proj = (const float*)d_in[8];
    const float* b_in_proj  = (const float*)d_in[9];
    const float* b_conv_w   = (const float*)d_in[10];
    const float* b_conv_b   = (const float*)d_in[11];
    const float* b_dt_bias  = (const float*)d_in[12];
    const float* b_A_log    = (const float*)d_in[13];
    const float* b_D        = (const float*)d_in[14];
    const float* b_norm_w   = (const float*)d_in[15];
    const float* b_out_proj = (const float*)d_in[16];
    const float* proj_w = (const float*)d_in[17];
    const float* proj_b = (const float*)d_in[18];
    const float* ln_w   = (const float*)d_in[19];
    const float* ln_b   = (const float*)d_in[20];

    float *pre, *dtraw;
    __half *zx16, *x16, *wip16, *wpr16, *wofT16, *wcomb16, *y16;
    cudaGetSymbolAddress((void**)&zx16, g_zx16);
    cudaGetSymbolAddress((void**)&dtraw, g_dtraw);
    cudaGetSymbolAddress((void**)&pre, g_pre);
    cudaGetSymbolAddress((void**)&x16, g_x16);
    cudaGetSymbolAddress((void**)&wip16, g_wip16);
    cudaGetSymbolAddress((void**)&wpr16, g_wpr16);
    cudaGetSymbolAddress((void**)&wofT16, g_wofT16);
    cudaGetSymbolAddress((void**)&wcomb16, g_wcomb16);
    cudaGetSymbolAddress((void**)&y16, g_y16);

    cudaFuncSetAttribute(gemm_f16, cudaFuncAttributeMaxDynamicSharedMemorySize, GT_SMEM);
    cudaFuncSetAttribute(scanB_kernel, cudaFuncAttributeMaxDynamicSharedMemorySize, SB_SMEM);

    // fp32 -> fp16 conversions + out_proj transposes
    f2h_kernel<<<2048, 256>>>(x, x16, BL * D_MODEL / 4);
    f2h_kernel<<<256, 256>>>(f_in_proj, wip16, D_IN_PROJ * D_MODEL / 4);
    f2h_kernel<<<256, 256>>>(b_in_proj, wip16 + (size_t)D_IN_PROJ * D_MODEL,
                             D_IN_PROJ * D_MODEL / 4);
    f2h_kernel<<<128, 256>>>(proj_w, wpr16, D_MODEL * D_INNER / 4);
    tr_f2h_kernel<<<dim3(32, 16, 2), dim3(32, 8)>>>(
        f_out_proj, b_out_proj, wofT16, wofT16 + (size_t)D_INNER * D_MODEL);

    // weight combine: wcomb[m][k + dir*1024] = proj_w[m][n + dir*512] * out_proj_dir[n][k]
    gemm_f16<<<dim3(D_INNER / 128, D_MODEL / 128, 2), 256, GT_SMEM>>>(
        wpr16, wpr16 + 512, D_INNER,
        wofT16, wofT16 + (size_t)D_INNER * D_MODEL, D_MODEL,
        wcomb16, wcomb16, 2 * D_INNER, D_INNER,
        D_INNER, D_MODEL, D_MODEL, 0, 0, 1, nullptr, nullptr, nullptr, 0);

    // in_proj both dirs -> fp16 zx + fp32 dt aux
    gemm_f16<<<dim3((D_IN_PROJ + 127) / 128, BL / 128, 2), 256, GT_SMEM>>>(
        x16, x16, D_MODEL, wip16, wip16 + (size_t)D_IN_PROJ * D_MODEL, D_MODEL,
        zx16, zx16 + (size_t)BL * D_IN_PROJ, D_IN_PROJ, 0,
        D_IN_PROJ, D_MODEL, D_MODEL, 0b10, 0, 1, nullptr, nullptr,
        dtraw, D_INNER + CONV_DIM);

    // fused conv + scan
    scanA_kernel<<<dim3(NC, NHEADS, 2 * B_SZ), 256>>>(
        f_A_log, b_A_log, f_conv_w, b_conv_w, f_conv_b, b_conv_b, f_dt_bias, b_dt_bias);
    scanMid_kernel<<<dim3(NHEADS, B_SZ, 2), 256>>>();
    scanB_kernel<<<dim3(NC, NHEADS, 2 * B_SZ), 256, SB_SMEM>>>(
        f_A_log, b_A_log, f_D, b_D,
        f_conv_w, b_conv_w, f_conv_b, b_conv_b, f_dt_bias, b_dt_bias);

    // gate + RMS normalization (in place on y16)
    gate_rms_kernel<<<dim3(BL, 2), 256>>>(f_norm_w, b_norm_w);

    // combined projection: pre = x + proj_b + [y_f | y_b(flip)] @ wcomb^T  (K=2048)
    gemm_f16<<<dim3(D_MODEL / 128, BL / 128, 1), 256, GT_SMEM>>>(
        y16, y16 + (size_t)BL * D_INNER, D_INNER,
        wcomb16, wcomb16, 2 * D_INNER,
        pre, pre, D_MODEL, 0,
        D_MODEL, 2 * D_INNER, D_INNER, 0b10, 0, 0, proj_b, x,
        nullptr, 0);

    ln_kernel<<<BL, 128>>>(ln_w, ln_b, (float*)d_out);
}

// round 13
// speedup vs baseline: 1.2510x; 1.0108x over previous
#include <cuda_runtime.h>
#include <cuda_fp16.h>
#include <cstdint>

#define B_SZ    8
#define L_SEQ   4096
#define D_MODEL 512
#define D_INNER 1024
#define NHEADS  16
#define HEADDIM 64
#define D_STATE 16
#define CONV_DIM 1056
#define D_IN_PROJ 2096
#define BL      (B_SZ * L_SEQ)
#define CS      64
#define NC      (L_SEQ / CS)
#define AUXZ    ((size_t)BL * 16)

// ---------------- scratch (device globals; no allocation allowed) ----------------
__device__ __half g_zx16[2][(size_t)BL * D_IN_PROJ];   // in_proj out (fp16)
__device__ float g_dtraw[2][(size_t)BL * 16];          // dt pre-softplus (fp32)
__device__ float g_pre[(size_t)BL * D_MODEL];
__device__ __half g_hstate[2][(size_t)B_SZ * NHEADS * NC * 1024];  // fp16 seeds
__device__ float g_P[2][B_SZ * NHEADS * NC];

__device__ __half g_x16[(size_t)BL * D_MODEL];
__device__ __half g_wip16[2][(size_t)D_IN_PROJ * D_MODEL];
__device__ __half g_wpr16[(size_t)D_MODEL * D_INNER];
__device__ __half g_wofT16[2][(size_t)D_INNER * D_MODEL]; // out_proj^T fp16
__device__ __half g_wcomb16[(size_t)D_MODEL * 2 * D_INNER]; // [512][2048]
__device__ __half g_y16[2][(size_t)BL * D_INNER];      // y (pre-gate) -> gated/normed

__device__ __forceinline__ int fliprow(int r) {
    return (r & ~(L_SEQ - 1)) | ((L_SEQ - 1) - (r & (L_SEQ - 1)));
}
__device__ __forceinline__ void cpa16(uint32_t dst, const void* src, int sz) {
    asm volatile("cp.async.cg.shared.global [%0], [%1], 16, %2;"
                 :: "r"(dst), "l"(src), "r"(sz));
}
#define CP_COMMIT() asm volatile("cp.async.commit_group;" ::: "memory")
#define CP_WAIT1()  asm volatile("cp.async.wait_group 1;" ::: "memory")

__device__ __forceinline__ uint2 pack_h4(float a, float b, float c, float d) {
    uint2 r;
    __half2 h0 = __floats2half2_rn(a, b);
    __half2 h1 = __floats2half2_rn(c, d);
    r.x = *(uint32_t*)&h0;
    r.y = *(uint32_t*)&h1;
    return r;
}
__device__ __forceinline__ float4 unpack_h4(uint2 v) {
    __half2 h0 = *(__half2*)&v.x;
    __half2 h1 = *(__half2*)&v.y;
    float2 a = __half22float2(h0);
    float2 b = __half22float2(h1);
    return make_float4(a.x, a.y, b.x, b.y);
}

// ---------------- fp32 -> fp16 convert (grid-stride, float4) ---------------------
__global__ void f2h_kernel(const float* __restrict__ src, __half* __restrict__ dst, int n4)
{
    for (int i = blockIdx.x * blockDim.x + threadIdx.x; i < n4; i += gridDim.x * blockDim.x) {
        float4 v = *(const float4*)(src + (size_t)i * 4);
        __half2* d = (__half2*)(dst + (size_t)i * 4);
        d[0] = __floats2half2_rn(v.x, v.y);
        d[1] = __floats2half2_rn(v.z, v.w);
    }
}

// ---------------- merged 4-segment fp32 -> fp16 convert --------------------------
__global__ void f2h_multi_kernel(const float* __restrict__ s0, const float* __restrict__ s1,
                                 const float* __restrict__ s2, const float* __restrict__ s3,
                                 __half* __restrict__ d0, __half* __restrict__ d1,
                                 __half* __restrict__ d2, __half* __restrict__ d3,
                                 int n0, int n1, int n2, int n3)
{
    const float* s;
    __half* d;
    int n4;
    switch (blockIdx.y) {
        case 0: s = s0; d = d0; n4 = n0; break;
        case 1: s = s1; d = d1; n4 = n1; break;
        case 2: s = s2; d = d2; n4 = n2; break;
        default: s = s3; d = d3; n4 = n3; break;
    }
    for (int i = blockIdx.x * blockDim.x + threadIdx.x; i < n4; i += gridDim.x * blockDim.x) {
        float4 v = *(const float4*)(s + (size_t)i * 4);
        __half2* dd = (__half2*)(d + (size_t)i * 4);
        dd[0] = __floats2half2_rn(v.x, v.y);
        dd[1] = __floats2half2_rn(v.z, v.w);
    }
}

// ------------- transpose fp32 [512][1024] -> fp16 [1024][512] --------------------
__global__ void tr_f2h_kernel(const float* __restrict__ s0, const float* __restrict__ s1,
                              __half* __restrict__ d0, __half* __restrict__ d1)
{
    const float* src = blockIdx.z ? s1 : s0;
    __half* dst = blockIdx.z ? d1 : d0;
    __shared__ float t[32][33];
    int c0 = blockIdx.x * 32, r0 = blockIdx.y * 32;
    int tx = threadIdx.x, ty = threadIdx.y;   // 32 x 8
    #pragma unroll
    for (int i = 0; i < 4; i++)
        t[ty + i * 8][tx] = src[(size_t)(r0 + ty + i * 8) * D_INNER + c0 + tx];
    __syncthreads();
    #pragma unroll
    for (int i = 0; i < 4; i++)
        dst[(size_t)(c0 + ty + i * 8) * D_MODEL + r0 + tx] =
            __float2half_rn(t[tx][ty + i * 8]);
}

// ============ fp16 mma.sync GEMM: C = A[M,K] @ W[N,K]^T (+bias +resid) ==========
// CTA tile 128x128, BK=64, 3-stage cp.async, 8 warps (4m x 2n), warp tile 32x64.
// grid.z selects direction set; ksplit<K enables dual-A k-stitching.
#define GT_STAGES 3
#define GT_ASZ 16384
#define GT_STG (2 * GT_ASZ)
#define GT_SMEM (GT_STAGES * GT_STG + 1024)

__global__ void __launch_bounds__(256, 2)
gemm_f16(const __half* __restrict__ A0, const __half* __restrict__ A1, int lda,
         const __half* __restrict__ W0, const __half* __restrict__ W1, int Wld,
         void* C0v, void* C1v, int ldc, int ccolstep,
         int N, int K, int ksplit,
         int flipAmask, int flipCmask, int halfOut,
         const float* __restrict__ bias,
         const float* __restrict__ resid,
         float* __restrict__ aux, int auxlo)
{
    extern __shared__ char dsm[];
    const uint32_t sb_raw = (uint32_t)__cvta_generic_to_shared(dsm);
    const uint32_t sb = (sb_raw + 1023u) & ~1023u;

    const int z = blockIdx.z;
    const int dual = (ksplit < K);
    const __half* Aa = dual ? A0 : (z ? A1 : A0);
    const __half* W = z ? W1 : W0;
    void* Cv = z ? C1v : C0v;
    const int ccol = z * ccolstep;
    const int flip_a = dual ? (flipAmask & 1) : ((flipAmask >> z) & 1);
    const int flip_b = (flipAmask >> 1) & 1;
    const int flipC = (flipCmask >> z) & 1;
    if (aux) aux += (size_t)z * AUXZ;

    const int tid = threadIdx.x;
    const int l   = tid & 31;
    const int w   = tid >> 5;
    const int wm  = w >> 1;
    const int wn  = w & 1;
    const int m0  = blockIdx.y * 128;
    const int n0  = blockIdx.x * 128;

    const int lr = l & 15;
    const int lc = l >> 4;
    const int lx = lr & 7;

    int arowA[4], arowB[4];
    #pragma unroll
    for (int i = 0; i < 4; i++) {
        int rr = (tid + i * 256) >> 3;
        int r = m0 + rr;
        arowA[i] = flip_a ? fliprow(r) : r;
        arowB[i] = flip_b ? fliprow(r) : r;
    }

    float acc[2][8][4];
    #pragma unroll
    for (int mi = 0; mi < 2; mi++)
        #pragma unroll
        for (int ni = 0; ni < 8; ni++)
            #pragma unroll
            for (int k = 0; k < 4; k++) acc[mi][ni][k] = 0.f;

    auto issue = [&](int s) {
        const int k0 = s * 64;
        const uint32_t base = sb + (s % GT_STAGES) * GT_STG;
        const __half* Ap = Aa;
        const int* ar = arowA;
        int kk = k0;
        if (dual && k0 >= ksplit) { Ap = A1; ar = arowB; kk = k0 - ksplit; }
        #pragma unroll
        for (int i = 0; i < 4; i++) {
            int q = tid + i * 256;
            int rr = q >> 3, ch = q & 7;
            int off = rr * 128 + ((ch ^ (rr & 7)) << 4);
            cpa16(base + off, Ap + (size_t)ar[i] * lda + kk + ch * 8, 16);
        }
        #pragma unroll
        for (int i = 0; i < 4; i++) {
            int q = tid + i * 256;
            int rr = q >> 3, ch = q & 7;
            int off = rr * 128 + ((ch ^ (rr & 7)) << 4);
            int n = n0 + rr;
            cpa16(base + GT_ASZ + off,
                  W + (size_t)(n < N ? n : 0) * Wld + k0 + ch * 8, (n < N) ? 16 : 0);
        }
    };
    auto compute = [&](int s) {
        const uint32_t Ab = sb + s * GT_STG;
        const uint32_t Bb = Ab + GT_ASZ;
        #pragma unroll
        for (int ks = 0; ks < 4; ks++) {
            const int chsel = ((ks << 1) | lc) ^ lx;
            uint32_t af[2][4];
            #pragma unroll
            for (int mi = 0; mi < 2; mi++) {
                uint32_t ad = Ab + (wm * 32 + mi * 16 + lr) * 128 + (chsel << 4);
                asm volatile("ldmatrix.sync.aligned.m8n8.x4.shared.b16 {%0,%1,%2,%3}, [%4];"
                    : "=r"(af[mi][0]), "=r"(af[mi][1]), "=r"(af[mi][2]), "=r"(af[mi][3])
                    : "r"(ad));
            }
            uint32_t bf[8][2];
            #pragma unroll
            for (int p = 0; p < 4; p++) {
                uint32_t bd = Bb + (wn * 64 + p * 16 + lr) * 128 + (chsel << 4);
                uint32_t q0, q1, q2, q3;
                asm volatile("ldmatrix.sync.aligned.m8n8.x4.shared.b16 {%0,%1,%2,%3}, [%4];"
                    : "=r"(q0), "=r"(q1), "=r"(q2), "=r"(q3) : "r"(bd));
                bf[2 * p][0] = q0;     bf[2 * p][1] = q2;
                bf[2 * p + 1][0] = q1; bf[2 * p + 1][1] = q3;
            }
            #pragma unroll
            for (int mi = 0; mi < 2; mi++)
                #pragma unroll
                for (int ni = 0; ni < 8; ni++) {
                    asm volatile(
                        "mma.sync.aligned.m16n8k16.row.col.f32.f16.f16.f32 "
                        "{%0,%1,%2,%3},{%4,%5,%6,%7},{%8,%9},{%0,%1,%2,%3};"
                        : "+f"(acc[mi][ni][0]), "+f"(acc[mi][ni][1]),
                          "+f"(acc[mi][ni][2]), "+f"(acc[mi][ni][3])
                        : "r"(af[mi][0]), "r"(af[mi][1]), "r"(af[mi][2]), "r"(af[mi][3]),
                          "r"(bf[ni][0]), "r"(bf[ni][1]));
                }
        }
    };

    const int KT = K / 64;
    issue(0); CP_COMMIT();
    issue(1); CP_COMMIT();
    for (int kt = 0; kt < KT; kt++) {
        CP_WAIT1();
        __syncthreads();
        if (kt + 2 < KT) issue(kt + 2);
        CP_COMMIT();
        compute(kt % GT_STAGES);
    }

    // epilogue
    #pragma unroll
    for (int mi = 0; mi < 2; mi++) {
        #pragma unroll
        for (int half = 0; half < 2; half++) {
            int r = m0 + wm * 32 + mi * 16 + (l >> 2) + half * 8;
            int cr = flipC ? fliprow(r) : r;
            const float* rp = resid + (size_t)cr * ldc + ccol;
            #pragma unroll
            for (int ni = 0; ni < 8; ni++) {
                int col = n0 + wn * 64 + ni * 8 + ((l & 3) << 1);
                if (col < N) {
                    float v0 = acc[mi][ni][half * 2 + 0];
                    float v1 = acc[mi][ni][half * 2 + 1];
                    if (bias)  { v0 += bias[col]; v1 += bias[col + 1]; }
                    if (resid) { v0 += rp[col];   v1 += rp[col + 1]; }
                    if (aux && col >= auxlo)
                        *(float2*)(aux + (size_t)cr * 16 + (col - auxlo)) =
                            make_float2(v0, v1);
                    if (halfOut) {
                        __half2* hp = (__half2*)((__half*)Cv + (size_t)cr * ldc + ccol + col);
                        *hp = __floats2half2_rn(v0, v1);
                    } else {
                        float* cp = (float*)Cv + (size_t)cr * ldc + ccol;
                        *(float2*)(cp + col) = make_float2(v0, v1);
                    }
                }
            }
        }
    }
}

// helper: silu
__device__ __forceinline__ float siluf(float v) { return v / (1.f + expf(-v)); }

// ======== fused conv + chunked scan pass A (local from zero) =====================
__global__ void __launch_bounds__(256)
scanA_kernel(const float* __restrict__ Al0, const float* __restrict__ Al1,
             const float* __restrict__ cw0, const float* __restrict__ cw1,
             const float* __restrict__ cb0, const float* __restrict__ cb1,
             const float* __restrict__ db0, const float* __restrict__ db1)
{
    const int c = blockIdx.x, h = blockIdx.y;
    const int b = blockIdx.z & (B_SZ - 1), dir = blockIdx.z >> 3;
    const int tid = threadIdx.x;
    const int p = tid >> 2, q = tid & 3;
    const float Aneg = -expf((dir ? Al1 : Al0)[h]);
    const float* conv_w  = dir ? cw1 : cw0;
    const float* conv_b  = dir ? cb1 : cb0;
    const float* dt_bias = dir ? db1 : db0;
    const __half* zx = g_zx16[dir];

    __shared__ float szx[CS + 3][80];
    __shared__ float sx[CS][64];
    __shared__ float sB[CS][16];
    __shared__ float sdt[CS];
    __shared__ float sdA[CS];
    __shared__ float scw[80 * 4];
    __shared__ float scb[80];

    const int l0 = c * CS;
    const size_t rowbase = (size_t)b * L_SEQ + l0;

    for (int idx = tid; idx < (CS + 3) * 80; idx += 256) {
        int s = idx / 80, ch = idx % 80;
        int ll = l0 + s - 3;
        int zc = (ch < 64) ? (D_INNER + h * 64 + ch) : (D_INNER + 1024 + (ch - 64));
        szx[s][ch] = (ll >= 0)
            ? __half2float(zx[((size_t)b * L_SEQ + ll) * D_IN_PROJ + zc]) : 0.f;
    }
    if (tid < 80) {
        int cc = (tid < 64) ? (h * 64 + tid) : (1024 + (tid - 64));
        scb[tid] = conv_b[cc];
        #pragma unroll
        for (int k = 0; k < 4; k++) scw[tid * 4 + k] = conv_w[cc * 4 + k];
    }
    if (tid < CS) {
        float raw = g_dtraw[dir][(rowbase + tid) * 16 + h] + dt_bias[h];
        float sp = (raw > 20.f) ? raw : log1pf(expf(raw));
        sdt[tid] = sp;
        sdA[tid] = expf(sp * Aneg);
    }
    __syncthreads();

    for (int idx = tid; idx < CS * 80; idx += 256) {
        int s = idx / 80, ch = idx % 80;
        float v = scb[ch];
        #pragma unroll
        for (int k = 0; k < 4; k++) v += szx[s + k][ch] * scw[ch * 4 + k];
        v = siluf(v);
        if (ch < 64) sx[s][ch] = v; else sB[s][ch - 64] = v;
    }
    __syncthreads();

    float h0 = 0.f, h1 = 0.f, h2 = 0.f, h3 = 0.f;
    #pragma unroll 4
    for (int s = 0; s < CS; s++) {
        float dA = sdA[s];
        float coef = sdt[s] * sx[s][p];
        float4 Bv = *(const float4*)&sB[s][q * 4];
        h0 = h0 * dA + coef * Bv.x;
        h1 = h1 * dA + coef * Bv.y;
        h2 = h2 * dA + coef * Bv.z;
        h3 = h3 * dA + coef * Bv.w;
    }
    size_t base = (((size_t)(b * NHEADS + h) * NC + c) << 10) + tid * 4;
    *(uint2*)&g_hstate[dir][base] = pack_h4(h0, h1, h2, h3);
    if (tid == 0) {
        float P = 1.f;
        for (int s = 0; s < CS; s++) P *= sdA[s];
        g_P[dir][(b * NHEADS + h) * NC + c] = P;
    }
}

// ======== chunked scan: middle combine (16-deep register prefetch ring) =========
#define MID_PF 16
__global__ void __launch_bounds__(256)
scanMid_kernel()
{
    const int h = blockIdx.x, b = blockIdx.y, dir = blockIdx.z;
    const int tid = threadIdx.x;
    __half* hs = g_hstate[dir];
    const size_t base = ((size_t)(b * NHEADS + h) * NC << 10) + tid * 4;
    __shared__ float sP[NC];
    if (tid < NC) sP[tid] = g_P[dir][(b * NHEADS + h) * NC + tid];
    __syncthreads();

    uint2 buf[MID_PF];
    #pragma unroll
    for (int i = 0; i < MID_PF; i++)
        buf[i] = *(const uint2*)&hs[base + ((size_t)i << 10)];

    float4 run = make_float4(0.f, 0.f, 0.f, 0.f);
    #pragma unroll
    for (int c = 0; c < NC; c++) {
        float4 endv = unpack_h4(buf[c % MID_PF]);
        if (c + MID_PF < NC)
            buf[c % MID_PF] = *(const uint2*)&hs[base + ((size_t)(c + MID_PF) << 10)];
        *(uint2*)&hs[base + ((size_t)c << 10)] = pack_h4(run.x, run.y, run.z, run.w);
        float P = sP[c];
        run.x = P * run.x + endv.x;
        run.y = P * run.y + endv.y;
        run.z = P * run.z + endv.z;
        run.w = P * run.w + endv.w;
    }
}

// ======== fused conv + chunked scan pass B (seeded, emit y fp16) =================
#define SB_SMEM ((67 * 96 + 64 * 64 + 1024 + 1024 + 64 + 64 + 384 + 96) * 4)

__global__ void __launch_bounds__(256)
scanB_kernel(const float* __restrict__ Al0, const float* __restrict__ Al1,
             const float* __restrict__ Dp0, const float* __restrict__ Dp1,
             const float* __restrict__ cw0, const float* __restrict__ cw1,
             const float* __restrict__ cb0, const float* __restrict__ cb1,
             const float* __restrict__ db0, const float* __restrict__ db1)
{
    extern __shared__ float sm[];
    float* szx = sm;                       // [67][96]
    float* sx  = sm + 67 * 96;             // [64][64]
    float* sB  = sx + 4096;                // [64][16]
    float* sC  = sB + 1024;                // [64][16]
    float* sdt = sC + 1024;                // [64]
    float* sdA = sdt + 64;                 // [64]
    float* scw = sdA + 64;                 // [96*4]
    float* scb = scw + 384;                // [96]
    float* sy  = szx;                      // reuse after conv phase

    const int c = blockIdx.x, h = blockIdx.y;
    const int b = blockIdx.z & (B_SZ - 1), dir = blockIdx.z >> 3;
    const int tid = threadIdx.x;
    const int p = tid >> 2, q = tid & 3;
    const float Aneg = -expf((dir ? Al1 : Al0)[h]);
    const float Dh = (dir ? Dp1 : Dp0)[h];
    const float* conv_w  = dir ? cw1 : cw0;
    const float* conv_b  = dir ? cb1 : cb0;
    const float* dt_bias = dir ? db1 : db0;
    const __half* zx = g_zx16[dir];

    const int l0 = c * CS;
    const size_t rowbase = (size_t)b * L_SEQ + l0;

    for (int idx = tid; idx < (CS + 3) * 96; idx += 256) {
        int s = idx / 96, ch = idx % 96;
        int ll = l0 + s - 3;
        int zc = (ch < 64) ? (D_INNER + h * 64 + ch) : (D_INNER + 1024 + (ch - 64));
        szx[s * 96 + ch] = (ll >= 0)
            ? __half2float(zx[((size_t)b * L_SEQ + ll) * D_IN_PROJ + zc]) : 0.f;
    }
    if (tid < 96) {
        int cc = (tid < 64) ? (h * 64 + tid) : (1024 + (tid - 64));
        scb[tid] = conv_b[cc];
        #pragma unroll
        for (int k = 0; k < 4; k++) scw[tid * 4 + k] = conv_w[cc * 4 + k];
    }
    if (tid < CS) {
        float raw = g_dtraw[dir][(rowbase + tid) * 16 + h] + dt_bias[h];
        float sp = (raw > 20.f) ? raw : log1pf(expf(raw));
        sdt[tid] = sp;
        sdA[tid] = expf(sp * Aneg);
    }
    float4 hin = unpack_h4(
        *(const uint2*)&g_hstate[dir][(((size_t)(b * NHEADS + h) * NC + c) << 10) + tid * 4]);
    __syncthreads();

    for (int idx = tid; idx < CS * 96; idx += 256) {
        int s = idx / 96, ch = idx % 96;
        float v = scb[ch];
        #pragma unroll
        for (int k = 0; k < 4; k++) v += szx[(s + k) * 96 + ch] * scw[ch * 4 + k];
        v = siluf(v);
        if (ch < 64) sx[s * 64 + ch] = v;
        else if (ch < 80) sB[s * 16 + (ch - 64)] = v;
        else sC[s * 16 + (ch - 80)] = v;
    }
    __syncthreads();

    float h0 = hin.x, h1 = hin.y, h2 = hin.z, h3 = hin.w;
    for (int s = 0; s < CS; s++) {
        float dA = sdA[s];
        float xv = sx[s * 64 + p];
        float coef = sdt[s] * xv;
        float4 Bv = *(const float4*)&sB[s * 16 + q * 4];
        float4 Cv = *(const float4*)&sC[s * 16 + q * 4];
        h0 = h0 * dA + coef * Bv.x;
        h1 = h1 * dA + coef * Bv.y;
        h2 = h2 * dA + coef * Bv.z;
        h3 = h3 * dA + coef * Bv.w;
        float yp = h0 * Cv.x + h1 * Cv.y + h2 * Cv.z + h3 * Cv.w;
        yp += __shfl_xor_sync(0xffffffffu, yp, 1);
        yp += __shfl_xor_sync(0xffffffffu, yp, 2);
        if (q == 0) sy[s * 64 + p] = yp + Dh * xv;
    }
    __syncthreads();
    // emit y as fp16 (pre-gating)
    for (int idx = tid; idx < CS * 32; idx += 256) {
        int s = idx >> 5, pp = (idx & 31) * 2;
        *(__half2*)&g_y16[dir][(rowbase + s) * D_INNER + h * 64 + pp] =
            __floats2half2_rn(sy[s * 64 + pp], sy[s * 64 + pp + 1]);
    }
}

// ------- y16 *= silu(z); RMSNorm * norm_w (in place on y16) ----------------------
__global__ void gate_rms_kernel(const float* __restrict__ nw0, const float* __restrict__ nw1)
{
    const int row = blockIdx.x, dir = blockIdx.y, tid = threadIdx.x;
    const float* norm_w = dir ? nw1 : nw0;
    __half2* yp = (__half2*)&g_y16[dir][(size_t)row * D_INNER + tid * 4];
    const __half2* zp = (const __half2*)&g_zx16[dir][(size_t)row * D_IN_PROJ + tid * 4];
    float2 y01 = __half22float2(yp[0]);
    float2 y23 = __half22float2(yp[1]);
    float2 z01 = __half22float2(zp[0]);
    float2 z23 = __half22float2(zp[1]);
    float4 yv;
    yv.x = y01.x * siluf(z01.x);
    yv.y = y01.y * siluf(z01.y);
    yv.z = y23.x * siluf(z23.x);
    yv.w = y23.y * siluf(z23.y);
    float ss = yv.x * yv.x + yv.y * yv.y + yv.z * yv.z + yv.w * yv.w;
    __shared__ float red[8];
    #pragma unroll
    for (int o = 16; o > 0; o >>= 1) ss += __shfl_xor_sync(0xffffffffu, ss, o);
    if ((tid & 31) == 0) red[tid >> 5] = ss;
    __syncthreads();
    float tot = red[0] + red[1] + red[2] + red[3] + red[4] + red[5] + red[6] + red[7];
    float sc = rsqrtf(tot * (1.f / D_INNER) + 1e-5f);
    float4 nv = *(const float4*)&norm_w[tid * 4];
    yp[0] = __floats2half2_rn(yv.x * sc * nv.x, yv.y * sc * nv.y);
    yp[1] = __floats2half2_rn(yv.z * sc * nv.z, yv.w * sc * nv.w);
}

// ---------------- final LayerNorm over 512 -> d_out ------------------------------
__global__ void ln_kernel(const float* __restrict__ ln_w, const float* __restrict__ ln_b,
                          float* __restrict__ out)
{
    const int row = blockIdx.x, tid = threadIdx.x;  // 128 threads
    const size_t base = (size_t)row * D_MODEL;
    float4 v = *(const float4*)&g_pre[base + tid * 4];
    float s = v.x + v.y + v.z + v.w;
    float s2 = v.x * v.x + v.y * v.y + v.z * v.z + v.w * v.w;
    __shared__ float rs[4], rs2[4];
    #pragma unroll
    for (int o = 16; o > 0; o >>= 1) {
        s  += __shfl_xor_sync(0xffffffffu, s, o);
        s2 += __shfl_xor_sync(0xffffffffu, s2, o);
    }
    if ((tid & 31) == 0) { rs[tid >> 5] = s; rs2[tid >> 5] = s2; }
    __syncthreads();
    float ts = rs[0] + rs[1] + rs[2] + rs[3];
    float ts2 = rs2[0] + rs2[1] + rs2[2] + rs2[3];
    float mu = ts * (1.f / D_MODEL);
    float var = ts2 * (1.f / D_MODEL) - mu * mu;
    float isd = rsqrtf(var + 1e-5f);
    float4 wv = *(const float4*)&ln_w[tid * 4];
    float4 bv = *(const float4*)&ln_b[tid * 4];
    float4 o;
    o.x = (v.x - mu) * isd * wv.x + bv.x;
    o.y = (v.y - mu) * isd * wv.y + bv.y;
    o.z = (v.z - mu) * isd * wv.z + bv.z;
    o.w = (v.w - mu) * isd * wv.w + bv.w;
    *(float4*)&out[base + tid * 4] = o;
}

// ---------------- orchestration ---------------------------------------------------
extern "C" void kernel_launch(void* const* d_in, const int* in_sizes, int n_in,
                              void* d_out, int out_size)
{
    const float* x      = (const float*)d_in[0];
    const float* f_in_proj  = (const float*)d_in[1];
    const float* f_conv_w   = (const float*)d_in[2];
    const float* f_conv_b   = (const float*)d_in[3];
    const float* f_dt_bias  = (const float*)d_in[4];
    const float* f_A_log    = (const float*)d_in[5];
    const float* f_D        = (const float*)d_in[6];
    const float* f_norm_w   = (const float*)d_in[7];
    const float* f_out_proj = (const float*)d_in[8];
    const float* b_in_proj  = (const float*)d_in[9];
    const float* b_conv_w   = (const float*)d_in[10];
    const float* b_conv_b   = (const float*)d_in[11];
    const float* b_dt_bias  = (const float*)d_in[12];
    const float* b_A_log    = (const float*)d_in[13];
    const float* b_D        = (const float*)d_in[14];
    const float* b_norm_w   = (const float*)d_in[15];
    const float* b_out_proj = (const float*)d_in[16];
    const float* proj_w = (const float*)d_in[17];
    const float* proj_b = (const float*)d_in[18];
    const float* ln_w   = (const float*)d_in[19];
    const float* ln_b   = (const float*)d_in[20];

    float *pre, *dtraw;
    __half *zx16, *x16, *wip16, *wpr16, *wofT16, *wcomb16, *y16;
    cudaGetSymbolAddress((void**)&zx16, g_zx16);
    cudaGetSymbolAddress((void**)&dtraw, g_dtraw);
    cudaGetSymbolAddress((void**)&pre, g_pre);
    cudaGetSymbolAddress((void**)&x16, g_x16);
    cudaGetSymbolAddress((void**)&wip16, g_wip16);
    cudaGetSymbolAddress((void**)&wpr16, g_wpr16);
    cudaGetSymbolAddress((void**)&wofT16, g_wofT16);
    cudaGetSymbolAddress((void**)&wcomb16, g_wcomb16);
    cudaGetSymbolAddress((void**)&y16, g_y16);

    cudaFuncSetAttribute(gemm_f16, cudaFuncAttributeMaxDynamicSharedMemorySize, GT_SMEM);
    cudaFuncSetAttribute(scanB_kernel, cudaFuncAttributeMaxDynamicSharedMemorySize, SB_SMEM);

    // fp32 -> fp16 conversions (x big; weights merged) + out_proj transposes
    f2h_kernel<<<2048, 256>>>(x, x16, BL * D_MODEL / 4);
    f2h_multi_kernel<<<dim3(256, 4), 256>>>(
        f_in_proj, b_in_proj, proj_w, proj_w,
        wip16, wip16 + (size_t)D_IN_PROJ * D_MODEL, wpr16, wpr16,
        D_IN_PROJ * D_MODEL / 4, D_IN_PROJ * D_MODEL / 4,
        D_MODEL * D_INNER / 4, 0);
    tr_f2h_kernel<<<dim3(32, 16, 2), dim3(32, 8)>>>(
        f_out_proj, b_out_proj, wofT16, wofT16 + (size_t)D_INNER * D_MODEL);

    // weight combine: wcomb[m][k + dir*1024] = proj_w[m][n + dir*512] * out_proj_dir[n][k]
    gemm_f16<<<dim3(D_INNER / 128, D_MODEL / 128, 2), 256, GT_SMEM>>>(
        wpr16, wpr16 + 512, D_INNER,
        wofT16, wofT16 + (size_t)D_INNER * D_MODEL, D_MODEL,
        wcomb16, wcomb16, 2 * D_INNER, D_INNER,
        D_INNER, D_MODEL, D_MODEL, 0, 0, 1, nullptr, nullptr, nullptr, 0);

    // in_proj both dirs -> fp16 zx + fp32 dt aux
    gemm_f16<<<dim3((D_IN_PROJ + 127) / 128, BL / 128, 2), 256, GT_SMEM>>>(
        x16, x16, D_MODEL, wip16, wip16 + (size_t)D_IN_PROJ * D_MODEL, D_MODEL,
        zx16, zx16 + (size_t)BL * D_IN_PROJ, D_IN_PROJ, 0,
        D_IN_PROJ, D_MODEL, D_MODEL, 0b10, 0, 1, nullptr, nullptr,
        dtraw, D_INNER + CONV_DIM);

    // fused conv + scan
    scanA_kernel<<<dim3(NC, NHEADS, 2 * B_SZ), 256>>>(
        f_A_log, b_A_log, f_conv_w, b_conv_w, f_conv_b, b_conv_b, f_dt_bias, b_dt_bias);
    scanMid_kernel<<<dim3(NHEADS, B_SZ, 2), 256>>>();
    scanB_kernel<<<dim3(NC, NHEADS, 2 * B_SZ), 256, SB_SMEM>>>(
        f_A_log, b_A_log, f_D, b_D,
        f_conv_w, b_conv_w, f_conv_b, b_conv_b, f_dt_bias, b_dt_bias);

    // gate + RMS normalization (in place on y16)
    gate_rms_kernel<<<dim3(BL, 2), 256>>>(f_norm_w, b_norm_w);

    // combined projection: pre = x + proj_b + [y_f | y_b(flip)] @ wcomb^T  (K=2048)
    gemm_f16<<<dim3(D_MODEL / 128, BL / 128, 1), 256, GT_SMEM>>>(
        y16, y16 + (size_t)BL * D_INNER, D_INNER,
        wcomb16, wcomb16, 2 * D_INNER,
        pre, pre, D_MODEL, 0,
        D_MODEL, 2 * D_INNER, D_INNER, 0b10, 0, 0, proj_b, x,
        nullptr, 0);

    ln_kernel<<<BL, 128>>>(ln_w, ln_b, (float*)d_out);
}

// round 14
// speedup vs baseline: 1.2709x; 1.0159x over previous
#include <cuda_runtime.h>
#include <cuda_fp16.h>
#include <cstdint>

#define B_SZ    8
#define L_SEQ   4096
#define D_MODEL 512
#define D_INNER 1024
#define NHEADS  16
#define HEADDIM 64
#define D_STATE 16
#define CONV_DIM 1056
#define D_IN_PROJ 2096
#define BL      (B_SZ * L_SEQ)
#define CS      64
#define NC      (L_SEQ / CS)
#define AUXZ    ((size_t)BL * 16)

// ---------------- scratch (device globals; no allocation allowed) ----------------
__device__ __half g_zx16[2][(size_t)BL * D_IN_PROJ];   // in_proj out (fp16)
__device__ float g_dtraw[2][(size_t)BL * 16];          // dt pre-softplus (fp32)
__device__ __half g_pre16[(size_t)BL * D_MODEL];       // pre-layernorm (fp16)
__device__ __half g_hstate[2][(size_t)B_SZ * NHEADS * NC * 1024];  // fp16 seeds
__device__ float g_P[2][B_SZ * NHEADS * NC];

__device__ __half g_x16[(size_t)BL * D_MODEL];
__device__ __half g_wip16[2][(size_t)D_IN_PROJ * D_MODEL];
__device__ __half g_wpr16[(size_t)D_MODEL * D_INNER];
__device__ __half g_wofT16[2][(size_t)D_INNER * D_MODEL]; // out_proj^T fp16
__device__ __half g_wcomb16[(size_t)D_MODEL * 2 * D_INNER]; // [512][2048]
__device__ __half g_y16[2][(size_t)BL * D_INNER];      // y (pre-gate) -> gated/normed

__device__ __forceinline__ int fliprow(int r) {
    return (r & ~(L_SEQ - 1)) | ((L_SEQ - 1) - (r & (L_SEQ - 1)));
}
__device__ __forceinline__ void cpa16(uint32_t dst, const void* src, int sz) {
    asm volatile("cp.async.cg.shared.global [%0], [%1], 16, %2;"
                 :: "r"(dst), "l"(src), "r"(sz));
}
#define CP_COMMIT() asm volatile("cp.async.commit_group;" ::: "memory")
#define CP_WAIT1()  asm volatile("cp.async.wait_group 1;" ::: "memory")

__device__ __forceinline__ uint2 pack_h4(float a, float b, float c, float d) {
    uint2 r;
    __half2 h0 = __floats2half2_rn(a, b);
    __half2 h1 = __floats2half2_rn(c, d);
    r.x = *(uint32_t*)&h0;
    r.y = *(uint32_t*)&h1;
    return r;
}
__device__ __forceinline__ float4 unpack_h4(uint2 v) {
    __half2 h0 = *(__half2*)&v.x;
    __half2 h1 = *(__half2*)&v.y;
    float2 a = __half22float2(h0);
    float2 b = __half22float2(h1);
    return make_float4(a.x, a.y, b.x, b.y);
}

// ---------------- fp32 -> fp16 convert (grid-stride, float4) ---------------------
__global__ void f2h_kernel(const float* __restrict__ src, __half* __restrict__ dst, int n4)
{
    for (int i = blockIdx.x * blockDim.x + threadIdx.x; i < n4; i += gridDim.x * blockDim.x) {
        float4 v = *(const float4*)(src + (size_t)i * 4);
        __half2* d = (__half2*)(dst + (size_t)i * 4);
        d[0] = __floats2half2_rn(v.x, v.y);
        d[1] = __floats2half2_rn(v.z, v.w);
    }
}

// ---------------- merged 4-segment fp32 -> fp16 convert --------------------------
__global__ void f2h_multi_kernel(const float* __restrict__ s0, const float* __restrict__ s1,
                                 const float* __restrict__ s2, const float* __restrict__ s3,
                                 __half* __restrict__ d0, __half* __restrict__ d1,
                                 __half* __restrict__ d2, __half* __restrict__ d3,
                                 int n0, int n1, int n2, int n3)
{
    const float* s;
    __half* d;
    int n4;
    switch (blockIdx.y) {
        case 0: s = s0; d = d0; n4 = n0; break;
        case 1: s = s1; d = d1; n4 = n1; break;
        case 2: s = s2; d = d2; n4 = n2; break;
        default: s = s3; d = d3; n4 = n3; break;
    }
    for (int i = blockIdx.x * blockDim.x + threadIdx.x; i < n4; i += gridDim.x * blockDim.x) {
        float4 v = *(const float4*)(s + (size_t)i * 4);
        __half2* dd = (__half2*)(d + (size_t)i * 4);
        dd[0] = __floats2half2_rn(v.x, v.y);
        dd[1] = __floats2half2_rn(v.z, v.w);
    }
}

// ------------- transpose fp32 [512][1024] -> fp16 [1024][512] --------------------
__global__ void tr_f2h_kernel(const float* __restrict__ s0, const float* __restrict__ s1,
                              __half* __restrict__ d0, __half* __restrict__ d1)
{
    const float* src = blockIdx.z ? s1 : s0;
    __half* dst = blockIdx.z ? d1 : d0;
    __shared__ float t[32][33];
    int c0 = blockIdx.x * 32, r0 = blockIdx.y * 32;
    int tx = threadIdx.x, ty = threadIdx.y;   // 32 x 8
    #pragma unroll
    for (int i = 0; i < 4; i++)
        t[ty + i * 8][tx] = src[(size_t)(r0 + ty + i * 8) * D_INNER + c0 + tx];
    __syncthreads();
    #pragma unroll
    for (int i = 0; i < 4; i++)
        dst[(size_t)(c0 + ty + i * 8) * D_MODEL + r0 + tx] =
            __float2half_rn(t[tx][ty + i * 8]);
}

// ============ fp16 mma.sync GEMM: C = A[M,K] @ W[N,K]^T (+bias +resid) ==========
// CTA tile 128x128, BK=64, 3-stage cp.async, 8 warps (4m x 2n), warp tile 32x64.
// grid.z selects direction set; ksplit<K enables dual-A k-stitching.
// resid: fp32 residual; residh: fp16 residual (used if non-null).
#define GT_STAGES 3
#define GT_ASZ 16384
#define GT_STG (2 * GT_ASZ)
#define GT_SMEM (GT_STAGES * GT_STG + 1024)

__global__ void __launch_bounds__(256, 2)
gemm_f16(const __half* __restrict__ A0, const __half* __restrict__ A1, int lda,
         const __half* __restrict__ W0, const __half* __restrict__ W1, int Wld,
         void* C0v, void* C1v, int ldc, int ccolstep,
         int N, int K, int ksplit,
         int flipAmask, int flipCmask, int halfOut,
         const float* __restrict__ bias,
         const float* __restrict__ resid,
         const __half* __restrict__ residh,
         float* __restrict__ aux, int auxlo)
{
    extern __shared__ char dsm[];
    const uint32_t sb_raw = (uint32_t)__cvta_generic_to_shared(dsm);
    const uint32_t sb = (sb_raw + 1023u) & ~1023u;

    const int z = blockIdx.z;
    const int dual = (ksplit < K);
    const __half* Aa = dual ? A0 : (z ? A1 : A0);
    const __half* W = z ? W1 : W0;
    void* Cv = z ? C1v : C0v;
    const int ccol = z * ccolstep;
    const int flip_a = dual ? (flipAmask & 1) : ((flipAmask >> z) & 1);
    const int flip_b = (flipAmask >> 1) & 1;
    const int flipC = (flipCmask >> z) & 1;
    if (aux) aux += (size_t)z * AUXZ;

    const int tid = threadIdx.x;
    const int l   = tid & 31;
    const int w   = tid >> 5;
    const int wm  = w >> 1;
    const int wn  = w & 1;
    const int m0  = blockIdx.y * 128;
    const int n0  = blockIdx.x * 128;

    const int lr = l & 15;
    const int lc = l >> 4;
    const int lx = lr & 7;

    int arowA[4], arowB[4];
    #pragma unroll
    for (int i = 0; i < 4; i++) {
        int rr = (tid + i * 256) >> 3;
        int r = m0 + rr;
        arowA[i] = flip_a ? fliprow(r) : r;
        arowB[i] = flip_b ? fliprow(r) : r;
    }

    float acc[2][8][4];
    #pragma unroll
    for (int mi = 0; mi < 2; mi++)
        #pragma unroll
        for (int ni = 0; ni < 8; ni++)
            #pragma unroll
            for (int k = 0; k < 4; k++) acc[mi][ni][k] = 0.f;

    auto issue = [&](int s) {
        const int k0 = s * 64;
        const uint32_t base = sb + (s % GT_STAGES) * GT_STG;
        const __half* Ap = Aa;
        const int* ar = arowA;
        int kk = k0;
        if (dual && k0 >= ksplit) { Ap = A1; ar = arowB; kk = k0 - ksplit; }
        #pragma unroll
        for (int i = 0; i < 4; i++) {
            int q = tid + i * 256;
            int rr = q >> 3, ch = q & 7;
            int off = rr * 128 + ((ch ^ (rr & 7)) << 4);
            cpa16(base + off, Ap + (size_t)ar[i] * lda + kk + ch * 8, 16);
        }
        #pragma unroll
        for (int i = 0; i < 4; i++) {
            int q = tid + i * 256;
            int rr = q >> 3, ch = q & 7;
            int off = rr * 128 + ((ch ^ (rr & 7)) << 4);
            int n = n0 + rr;
            cpa16(base + GT_ASZ + off,
                  W + (size_t)(n < N ? n : 0) * Wld + k0 + ch * 8, (n < N) ? 16 : 0);
        }
    };
    auto compute = [&](int s) {
        const uint32_t Ab = sb + s * GT_STG;
        const uint32_t Bb = Ab + GT_ASZ;
        #pragma unroll
        for (int ks = 0; ks < 4; ks++) {
            const int chsel = ((ks << 1) | lc) ^ lx;
            uint32_t af[2][4];
            #pragma unroll
            for (int mi = 0; mi < 2; mi++) {
                uint32_t ad = Ab + (wm * 32 + mi * 16 + lr) * 128 + (chsel << 4);
                asm volatile("ldmatrix.sync.aligned.m8n8.x4.shared.b16 {%0,%1,%2,%3}, [%4];"
                    : "=r"(af[mi][0]), "=r"(af[mi][1]), "=r"(af[mi][2]), "=r"(af[mi][3])
                    : "r"(ad));
            }
            uint32_t bf[8][2];
            #pragma unroll
            for (int p = 0; p < 4; p++) {
                uint32_t bd = Bb + (wn * 64 + p * 16 + lr) * 128 + (chsel << 4);
                uint32_t q0, q1, q2, q3;
                asm volatile("ldmatrix.sync.aligned.m8n8.x4.shared.b16 {%0,%1,%2,%3}, [%4];"
                    : "=r"(q0), "=r"(q1), "=r"(q2), "=r"(q3) : "r"(bd));
                bf[2 * p][0] = q0;     bf[2 * p][1] = q2;
                bf[2 * p + 1][0] = q1; bf[2 * p + 1][1] = q3;
            }
            #pragma unroll
            for (int mi = 0; mi < 2; mi++)
                #pragma unroll
                for (int ni = 0; ni < 8; ni++) {
                    asm volatile(
                        "mma.sync.aligned.m16n8k16.row.col.f32.f16.f16.f32 "
                        "{%0,%1,%2,%3},{%4,%5,%6,%7},{%8,%9},{%0,%1,%2,%3};"
                        : "+f"(acc[mi][ni][0]), "+f"(acc[mi][ni][1]),
                          "+f"(acc[mi][ni][2]), "+f"(acc[mi][ni][3])
                        : "r"(af[mi][0]), "r"(af[mi][1]), "r"(af[mi][2]), "r"(af[mi][3]),
                          "r"(bf[ni][0]), "r"(bf[ni][1]));
                }
        }
    };

    const int KT = K / 64;
    issue(0); CP_COMMIT();
    issue(1); CP_COMMIT();
    for (int kt = 0; kt < KT; kt++) {
        CP_WAIT1();
        __syncthreads();
        if (kt + 2 < KT) issue(kt + 2);
        CP_COMMIT();
        compute(kt % GT_STAGES);
    }

    // epilogue
    #pragma unroll
    for (int mi = 0; mi < 2; mi++) {
        #pragma unroll
        for (int half = 0; half < 2; half++) {
            int r = m0 + wm * 32 + mi * 16 + (l >> 2) + half * 8;
            int cr = flipC ? fliprow(r) : r;
            const float* rp = resid + (size_t)cr * ldc + ccol;
            const __half* rh = residh + (size_t)cr * ldc + ccol;
            #pragma unroll
            for (int ni = 0; ni < 8; ni++) {
                int col = n0 + wn * 64 + ni * 8 + ((l & 3) << 1);
                if (col < N) {
                    float v0 = acc[mi][ni][half * 2 + 0];
                    float v1 = acc[mi][ni][half * 2 + 1];
                    if (bias)  { v0 += bias[col]; v1 += bias[col + 1]; }
                    if (residh) {
                        float2 rv = __half22float2(*(const __half2*)(rh + col));
                        v0 += rv.x; v1 += rv.y;
                    } else if (resid) {
                        v0 += rp[col]; v1 += rp[col + 1];
                    }
                    if (aux && col >= auxlo)
                        *(float2*)(aux + (size_t)cr * 16 + (col - auxlo)) =
                            make_float2(v0, v1);
                    if (halfOut) {
                        __half2* hp = (__half2*)((__half*)Cv + (size_t)cr * ldc + ccol + col);
                        *hp = __floats2half2_rn(v0, v1);
                    } else {
                        float* cp = (float*)Cv + (size_t)cr * ldc + ccol;
                        *(float2*)(cp + col) = make_float2(v0, v1);
                    }
                }
            }
        }
    }
}

// helper: silu
__device__ __forceinline__ float siluf(float v) { return v / (1.f + expf(-v)); }

// ======== fused conv + chunked scan pass A (local from zero) =====================
__global__ void __launch_bounds__(256)
scanA_kernel(const float* __restrict__ Al0, const float* __restrict__ Al1,
             const float* __restrict__ cw0, const float* __restrict__ cw1,
             const float* __restrict__ cb0, const float* __restrict__ cb1,
             const float* __restrict__ db0, const float* __restrict__ db1)
{
    const int c = blockIdx.x, h = blockIdx.y;
    const int b = blockIdx.z & (B_SZ - 1), dir = blockIdx.z >> 3;
    const int tid = threadIdx.x;
    const int p = tid >> 2, q = tid & 3;
    const float Aneg = -expf((dir ? Al1 : Al0)[h]);
    const float* conv_w  = dir ? cw1 : cw0;
    const float* conv_b  = dir ? cb1 : cb0;
    const float* dt_bias = dir ? db1 : db0;
    const __half* zx = g_zx16[dir];

    __shared__ float szx[CS + 3][80];
    __shared__ float sx[CS][64];
    __shared__ float sB[CS][16];
    __shared__ float sdt[CS];
    __shared__ float sdA[CS];
    __shared__ float scw[80 * 4];
    __shared__ float scb[80];

    const int l0 = c * CS;
    const size_t rowbase = (size_t)b * L_SEQ + l0;

    for (int idx = tid; idx < (CS + 3) * 80; idx += 256) {
        int s = idx / 80, ch = idx % 80;
        int ll = l0 + s - 3;
        int zc = (ch < 64) ? (D_INNER + h * 64 + ch) : (D_INNER + 1024 + (ch - 64));
        szx[s][ch] = (ll >= 0)
            ? __half2float(zx[((size_t)b * L_SEQ + ll) * D_IN_PROJ + zc]) : 0.f;
    }
    if (tid < 80) {
        int cc = (tid < 64) ? (h * 64 + tid) : (1024 + (tid - 64));
        scb[tid] = conv_b[cc];
        #pragma unroll
        for (int k = 0; k < 4; k++) scw[tid * 4 + k] = conv_w[cc * 4 + k];
    }
    if (tid < CS) {
        float raw = g_dtraw[dir][(rowbase + tid) * 16 + h] + dt_bias[h];
        float sp = (raw > 20.f) ? raw : log1pf(expf(raw));
        sdt[tid] = sp;
        sdA[tid] = expf(sp * Aneg);
    }
    __syncthreads();

    for (int idx = tid; idx < CS * 80; idx += 256) {
        int s = idx / 80, ch = idx % 80;
        float v = scb[ch];
        #pragma unroll
        for (int k = 0; k < 4; k++) v += szx[s + k][ch] * scw[ch * 4 + k];
        v = siluf(v);
        if (ch < 64) sx[s][ch] = v; else sB[s][ch - 64] = v;
    }
    __syncthreads();

    float h0 = 0.f, h1 = 0.f, h2 = 0.f, h3 = 0.f;
    #pragma unroll 4
    for (int s = 0; s < CS; s++) {
        float dA = sdA[s];
        float coef = sdt[s] * sx[s][p];
        float4 Bv = *(const float4*)&sB[s][q * 4];
        h0 = h0 * dA + coef * Bv.x;
        h1 = h1 * dA + coef * Bv.y;
        h2 = h2 * dA + coef * Bv.z;
        h3 = h3 * dA + coef * Bv.w;
    }
    size_t base = (((size_t)(b * NHEADS + h) * NC + c) << 10) + tid * 4;
    *(uint2*)&g_hstate[dir][base] = pack_h4(h0, h1, h2, h3);
    if (tid == 0) {
        float P = 1.f;
        for (int s = 0; s < CS; s++) P *= sdA[s];
        g_P[dir][(b * NHEADS + h) * NC + c] = P;
    }
}

// ======== chunked scan: middle combine (16-deep register prefetch ring) =========
#define MID_PF 16
__global__ void __launch_bounds__(256)
scanMid_kernel()
{
    const int h = blockIdx.x, b = blockIdx.y, dir = blockIdx.z;
    const int tid = threadIdx.x;
    __half* hs = g_hstate[dir];
    const size_t base = ((size_t)(b * NHEADS + h) * NC << 10) + tid * 4;
    __shared__ float sP[NC];
    if (tid < NC) sP[tid] = g_P[dir][(b * NHEADS + h) * NC + tid];
    __syncthreads();

    uint2 buf[MID_PF];
    #pragma unroll
    for (int i = 0; i < MID_PF; i++)
        buf[i] = *(const uint2*)&hs[base + ((size_t)i << 10)];

    float4 run = make_float4(0.f, 0.f, 0.f, 0.f);
    #pragma unroll
    for (int c = 0; c < NC; c++) {
        float4 endv = unpack_h4(buf[c % MID_PF]);
        if (c + MID_PF < NC)
            buf[c % MID_PF] = *(const uint2*)&hs[base + ((size_t)(c + MID_PF) << 10)];
        *(uint2*)&hs[base + ((size_t)c << 10)] = pack_h4(run.x, run.y, run.z, run.w);
        float P = sP[c];
        run.x = P * run.x + endv.x;
        run.y = P * run.y + endv.y;
        run.z = P * run.z + endv.z;
        run.w = P * run.w + endv.w;
    }
}

// ======== fused conv + chunked scan pass B (seeded, emit y fp16) =================
#define SB_SMEM ((67 * 96 + 64 * 64 + 1024 + 1024 + 64 + 64 + 384 + 96) * 4)

__global__ void __launch_bounds__(256)
scanB_kernel(const float* __restrict__ Al0, const float* __restrict__ Al1,
             const float* __restrict__ Dp0, const float* __restrict__ Dp1,
             const float* __restrict__ cw0, const float* __restrict__ cw1,
             const float* __restrict__ cb0, const float* __restrict__ cb1,
             const float* __restrict__ db0, const float* __restrict__ db1)
{
    extern __shared__ float sm[];
    float* szx = sm;                       // [67][96]
    float* sx  = sm + 67 * 96;             // [64][64]
    float* sB  = sx + 4096;                // [64][16]
    float* sC  = sB + 1024;                // [64][16]
    float* sdt = sC + 1024;                // [64]
    float* sdA = sdt + 64;                 // [64]
    float* scw = sdA + 64;                 // [96*4]
    float* scb = scw + 384;                // [96]
    float* sy  = szx;                      // reuse after conv phase

    const int c = blockIdx.x, h = blockIdx.y;
    const int b = blockIdx.z & (B_SZ - 1), dir = blockIdx.z >> 3;
    const int tid = threadIdx.x;
    const int p = tid >> 2, q = tid & 3;
    const float Aneg = -expf((dir ? Al1 : Al0)[h]);
    const float Dh = (dir ? Dp1 : Dp0)[h];
    const float* conv_w  = dir ? cw1 : cw0;
    const float* conv_b  = dir ? cb1 : cb0;
    const float* dt_bias = dir ? db1 : db0;
    const __half* zx = g_zx16[dir];

    const int l0 = c * CS;
    const size_t rowbase = (size_t)b * L_SEQ + l0;

    for (int idx = tid; idx < (CS + 3) * 96; idx += 256) {
        int s = idx / 96, ch = idx % 96;
        int ll = l0 + s - 3;
        int zc = (ch < 64) ? (D_INNER + h * 64 + ch) : (D_INNER + 1024 + (ch - 64));
        szx[s * 96 + ch] = (ll >= 0)
            ? __half2float(zx[((size_t)b * L_SEQ + ll) * D_IN_PROJ + zc]) : 0.f;
    }
    if (tid < 96) {
        int cc = (tid < 64) ? (h * 64 + tid) : (1024 + (tid - 64));
        scb[tid] = conv_b[cc];
        #pragma unroll
        for (int k = 0; k < 4; k++) scw[tid * 4 + k] = conv_w[cc * 4 + k];
    }
    if (tid < CS) {
        float raw = g_dtraw[dir][(rowbase + tid) * 16 + h] + dt_bias[h];
        float sp = (raw > 20.f) ? raw : log1pf(expf(raw));
        sdt[tid] = sp;
        sdA[tid] = expf(sp * Aneg);
    }
    float4 hin = unpack_h4(
        *(const uint2*)&g_hstate[dir][(((size_t)(b * NHEADS + h) * NC + c) << 10) + tid * 4]);
    __syncthreads();

    for (int idx = tid; idx < CS * 96; idx += 256) {
        int s = idx / 96, ch = idx % 96;
        float v = scb[ch];
        #pragma unroll
        for (int k = 0; k < 4; k++) v += szx[(s + k) * 96 + ch] * scw[ch * 4 + k];
        v = siluf(v);
        if (ch < 64) sx[s * 64 + ch] = v;
        else if (ch < 80) sB[s * 16 + (ch - 64)] = v;
        else sC[s * 16 + (ch - 80)] = v;
    }
    __syncthreads();

    float h0 = hin.x, h1 = hin.y, h2 = hin.z, h3 = hin.w;
    for (int s = 0; s < CS; s++) {
        float dA = sdA[s];
        float xv = sx[s * 64 + p];
        float coef = sdt[s] * xv;
        float4 Bv = *(const float4*)&sB[s * 16 + q * 4];
        float4 Cv = *(const float4*)&sC[s * 16 + q * 4];
        h0 = h0 * dA + coef * Bv.x;
        h1 = h1 * dA + coef * Bv.y;
        h2 = h2 * dA + coef * Bv.z;
        h3 = h3 * dA + coef * Bv.w;
        float yp = h0 * Cv.x + h1 * Cv.y + h2 * Cv.z + h3 * Cv.w;
        yp += __shfl_xor_sync(0xffffffffu, yp, 1);
        yp += __shfl_xor_sync(0xffffffffu, yp, 2);
        if (q == 0) sy[s * 64 + p] = yp + Dh * xv;
    }
    __syncthreads();
    // emit y as fp16 (pre-gating)
    for (int idx = tid; idx < CS * 32; idx += 256) {
        int s = idx >> 5, pp = (idx & 31) * 2;
        *(__half2*)&g_y16[dir][(rowbase + s) * D_INNER + h * 64 + pp] =
            __floats2half2_rn(sy[s * 64 + pp], sy[s * 64 + pp + 1]);
    }
}

// ------- y16 *= silu(z); RMSNorm * norm_w (in place on y16) ----------------------
__global__ void gate_rms_kernel(const float* __restrict__ nw0, const float* __restrict__ nw1)
{
    const int row = blockIdx.x, dir = blockIdx.y, tid = threadIdx.x;
    const float* norm_w = dir ? nw1 : nw0;
    __half2* yp = (__half2*)&g_y16[dir][(size_t)row * D_INNER + tid * 4];
    const __half2* zp = (const __half2*)&g_zx16[dir][(size_t)row * D_IN_PROJ + tid * 4];
    float2 y01 = __half22float2(yp[0]);
    float2 y23 = __half22float2(yp[1]);
    float2 z01 = __half22float2(zp[0]);
    float2 z23 = __half22float2(zp[1]);
    float4 yv;
    yv.x = y01.x * siluf(z01.x);
    yv.y = y01.y * siluf(z01.y);
    yv.z = y23.x * siluf(z23.x);
    yv.w = y23.y * siluf(z23.y);
    float ss = yv.x * yv.x + yv.y * yv.y + yv.z * yv.z + yv.w * yv.w;
    __shared__ float red[8];
    #pragma unroll
    for (int o = 16; o > 0; o >>= 1) ss += __shfl_xor_sync(0xffffffffu, ss, o);
    if ((tid & 31) == 0) red[tid >> 5] = ss;
    __syncthreads();
    float tot = red[0] + red[1] + red[2] + red[3] + red[4] + red[5] + red[6] + red[7];
    float sc = rsqrtf(tot * (1.f / D_INNER) + 1e-5f);
    float4 nv = *(const float4*)&norm_w[tid * 4];
    yp[0] = __floats2half2_rn(yv.x * sc * nv.x, yv.y * sc * nv.y);
    yp[1] = __floats2half2_rn(yv.z * sc * nv.z, yv.w * sc * nv.w);
}

// ---------------- final LayerNorm over 512 (fp16 in) -> d_out --------------------
__global__ void ln_kernel(const float* __restrict__ ln_w, const float* __restrict__ ln_b,
                          float* __restrict__ out)
{
    const int row = blockIdx.x, tid = threadIdx.x;  // 128 threads
    const size_t base = (size_t)row * D_MODEL;
    const __half2* pp = (const __half2*)&g_pre16[base + tid * 4];
    float2 a = __half22float2(pp[0]);
    float2 bb = __half22float2(pp[1]);
    float4 v = make_float4(a.x, a.y, bb.x, bb.y);
    float s = v.x + v.y + v.z + v.w;
    float s2 = v.x * v.x + v.y * v.y + v.z * v.z + v.w * v.w;
    __shared__ float rs[4], rs2[4];
    #pragma unroll
    for (int o = 16; o > 0; o >>= 1) {
        s  += __shfl_xor_sync(0xffffffffu, s, o);
        s2 += __shfl_xor_sync(0xffffffffu, s2, o);
    }
    if ((tid & 31) == 0) { rs[tid >> 5] = s; rs2[tid >> 5] = s2; }
    __syncthreads();
    float ts = rs[0] + rs[1] + rs[2] + rs[3];
    float ts2 = rs2[0] + rs2[1] + rs2[2] + rs2[3];
    float mu = ts * (1.f / D_MODEL);
    float var = ts2 * (1.f / D_MODEL) - mu * mu;
    float isd = rsqrtf(var + 1e-5f);
    float4 wv = *(const float4*)&ln_w[tid * 4];
    float4 bv = *(const float4*)&ln_b[tid * 4];
    float4 o;
    o.x = (v.x - mu) * isd * wv.x + bv.x;
    o.y = (v.y - mu) * isd * wv.y + bv.y;
    o.z = (v.z - mu) * isd * wv.z + bv.z;
    o.w = (v.w - mu) * isd * wv.w + bv.w;
    *(float4*)&out[base + tid * 4] = o;
}

// ---------------- orchestration ---------------------------------------------------
extern "C" void kernel_launch(void* const* d_in, const int* in_sizes, int n_in,
                              void* d_out, int out_size)
{
    const float* x      = (const float*)d_in[0];
    const float* f_in_proj  = (const float*)d_in[1];
    const float* f_conv_w   = (const float*)d_in[2];
    const float* f_conv_b   = (const float*)d_in[3];
    const float* f_dt_bias  = (const float*)d_in[4];
    const float* f_A_log    = (const float*)d_in[5];
    const float* f_D        = (const float*)d_in[6];
    const float* f_norm_w   = (const float*)d_in[7];
    const float* f_out_proj = (const float*)d_in[8];
    const float* b_in_proj  = (const float*)d_in[9];
    const float* b_conv_w   = (const float*)d_in[10];
    const float* b_conv_b   = (const float*)d_in[11];
    const float* b_dt_bias  = (const float*)d_in[12];
    const float* b_A_log    = (const float*)d_in[13];
    const float* b_D        = (const float*)d_in[14];
    const float* b_norm_w   = (const float*)d_in[15];
    const float* b_out_proj = (const float*)d_in[16];
    const float* proj_w = (const float*)d_in[17];
    const float* proj_b = (const float*)d_in[18];
    const float* ln_w   = (const float*)d_in[19];
    const float* ln_b   = (const float*)d_in[20];

    float *dtraw;
    __half *zx16, *pre16, *x16, *wip16, *wpr16, *wofT16, *wcomb16, *y16;
    cudaGetSymbolAddress((void**)&zx16, g_zx16);
    cudaGetSymbolAddress((void**)&dtraw, g_dtraw);
    cudaGetSymbolAddress((void**)&pre16, g_pre16);
    cudaGetSymbolAddress((void**)&x16, g_x16);
    cudaGetSymbolAddress((void**)&wip16, g_wip16);
    cudaGetSymbolAddress((void**)&wpr16, g_wpr16);
    cudaGetSymbolAddress((void**)&wofT16, g_wofT16);
    cudaGetSymbolAddress((void**)&wcomb16, g_wcomb16);
    cudaGetSymbolAddress((void**)&y16, g_y16);

    cudaFuncSetAttribute(gemm_f16, cudaFuncAttributeMaxDynamicSharedMemorySize, GT_SMEM);
    cudaFuncSetAttribute(scanB_kernel, cudaFuncAttributeMaxDynamicSharedMemorySize, SB_SMEM);

    // fp32 -> fp16 conversions (x big; weights merged) + out_proj transposes
    f2h_kernel<<<2048, 256>>>(x, x16, BL * D_MODEL / 4);
    f2h_multi_kernel<<<dim3(256, 4), 256>>>(
        f_in_proj, b_in_proj, proj_w, proj_w,
        wip16, wip16 + (size_t)D_IN_PROJ * D_MODEL, wpr16, wpr16,
        D_IN_PROJ * D_MODEL / 4, D_IN_PROJ * D_MODEL / 4,
        D_MODEL * D_INNER / 4, 0);
    tr_f2h_kernel<<<dim3(32, 16, 2), dim3(32, 8)>>>(
        f_out_proj, b_out_proj, wofT16, wofT16 + (size_t)D_INNER * D_MODEL);

    // weight combine: wcomb[m][k + dir*1024] = proj_w[m][n + dir*512] * out_proj_dir[n][k]
    gemm_f16<<<dim3(D_INNER / 128, D_MODEL / 128, 2), 256, GT_SMEM>>>(
        wpr16, wpr16 + 512, D_INNER,
        wofT16, wofT16 + (size_t)D_INNER * D_MODEL, D_MODEL,
        wcomb16, wcomb16, 2 * D_INNER, D_INNER,
        D_INNER, D_MODEL, D_MODEL, 0, 0, 1, nullptr, nullptr, nullptr, nullptr, 0);

    // in_proj both dirs -> fp16 zx + fp32 dt aux
    gemm_f16<<<dim3((D_IN_PROJ + 127) / 128, BL / 128, 2), 256, GT_SMEM>>>(
        x16, x16, D_MODEL, wip16, wip16 + (size_t)D_IN_PROJ * D_MODEL, D_MODEL,
        zx16, zx16 + (size_t)BL * D_IN_PROJ, D_IN_PROJ, 0,
        D_IN_PROJ, D_MODEL, D_MODEL, 0b10, 0, 1, nullptr, nullptr, nullptr,
        dtraw, D_INNER + CONV_DIM);

    // fused conv + scan
    scanA_kernel<<<dim3(NC, NHEADS, 2 * B_SZ), 256>>>(
        f_A_log, b_A_log, f_conv_w, b_conv_w, f_conv_b, b_conv_b, f_dt_bias, b_dt_bias);
    scanMid_kernel<<<dim3(NHEADS, B_SZ, 2), 256>>>();
    scanB_kernel<<<dim3(NC, NHEADS, 2 * B_SZ), 256, SB_SMEM>>>(
        f_A_log, b_A_log, f_D, b_D,
        f_conv_w, b_conv_w, f_conv_b, b_conv_b, f_dt_bias, b_dt_bias);

    // gate + RMS normalization (in place on y16)
    gate_rms_kernel<<<dim3(BL, 2), 256>>>(f_norm_w, b_norm_w);

    // combined projection: pre16 = x16 + proj_b + [y_f | y_b(flip)] @ wcomb^T (K=2048)
    gemm_f16<<<dim3(D_MODEL / 128, BL / 128, 1), 256, GT_SMEM>>>(
        y16, y16 + (size_t)BL * D_INNER, D_INNER,
        wcomb16, wcomb16, 2 * D_INNER,
        pre16, pre16, D_MODEL, 0,
        D_MODEL, 2 * D_INNER, D_INNER, 0b10, 0, 1, proj_b, nullptr, x16,
        nullptr, 0);

    ln_kernel<<<BL, 128>>>(ln_w, ln_b, (float*)d_out);
}

// round 15
// speedup vs baseline: 1.3524x; 1.0641x over previous
#include <cuda_runtime.h>
#include <cuda_fp16.h>
#include <cstdint>

#define B_SZ    8
#define L_SEQ   4096
#define D_MODEL 512
#define D_INNER 1024
#define NHEADS  16
#define HEADDIM 64
#define D_STATE 16
#define CONV_DIM 1056
#define D_IN_PROJ 2096
#define BL      (B_SZ * L_SEQ)
#define CS      64
#define NC      (L_SEQ / CS)
#define AUXZ    ((size_t)BL * 16)

// ---------------- scratch (device globals; no allocation allowed) ----------------
__device__ __half g_zx16[2][(size_t)BL * D_IN_PROJ];   // in_proj out (fp16)
__device__ float g_dtraw[2][(size_t)BL * 16];          // dt pre-softplus (fp32)
__device__ __half g_pre16[(size_t)BL * D_MODEL];       // pre-layernorm (fp16)
__device__ __half g_hstate[2][(size_t)B_SZ * NHEADS * NC * 1024];  // fp16 seeds
__device__ float g_P[2][B_SZ * NHEADS * NC];

__device__ __half g_x16[(size_t)BL * D_MODEL];
__device__ __half g_wip16[2][(size_t)D_IN_PROJ * D_MODEL];
__device__ __half g_wpr16[(size_t)D_MODEL * D_INNER];
__device__ __half g_wofT16[2][(size_t)D_INNER * D_MODEL]; // out_proj^T fp16
__device__ __half g_wcomb16[(size_t)D_MODEL * 2 * D_INNER]; // [512][2048]
__device__ __half g_y16[2][(size_t)BL * D_INNER];      // y (pre-gate) -> gated/normed

__device__ __forceinline__ int fliprow(int r) {
    return (r & ~(L_SEQ - 1)) | ((L_SEQ - 1) - (r & (L_SEQ - 1)));
}
__device__ __forceinline__ void cpa16(uint32_t dst, const void* src, int sz) {
    asm volatile("cp.async.cg.shared.global [%0], [%1], 16, %2;"
                 :: "r"(dst), "l"(src), "r"(sz));
}
#define CP_COMMIT() asm volatile("cp.async.commit_group;" ::: "memory")
#define CP_WAIT1()  asm volatile("cp.async.wait_group 1;" ::: "memory")

__device__ __forceinline__ uint2 pack_h4(float a, float b, float c, float d) {
    uint2 r;
    __half2 h0 = __floats2half2_rn(a, b);
    __half2 h1 = __floats2half2_rn(c, d);
    r.x = *(uint32_t*)&h0;
    r.y = *(uint32_t*)&h1;
    return r;
}
__device__ __forceinline__ float4 unpack_h4(uint2 v) {
    __half2 h0 = *(__half2*)&v.x;
    __half2 h1 = *(__half2*)&v.y;
    float2 a = __half22float2(h0);
    float2 b = __half22float2(h1);
    return make_float4(a.x, a.y, b.x, b.y);
}

// ---------------- merged 4-segment fp32 -> fp16 convert --------------------------
__global__ void f2h_multi_kernel(const float* __restrict__ s0, const float* __restrict__ s1,
                                 const float* __restrict__ s2, const float* __restrict__ s3,
                                 __half* __restrict__ d0, __half* __restrict__ d1,
                                 __half* __restrict__ d2, __half* __restrict__ d3,
                                 int n0, int n1, int n2, int n3)
{
    const float* s;
    __half* d;
    int n4;
    switch (blockIdx.y) {
        case 0: s = s0; d = d0; n4 = n0; break;
        case 1: s = s1; d = d1; n4 = n1; break;
        case 2: s = s2; d = d2; n4 = n2; break;
        default: s = s3; d = d3; n4 = n3; break;
    }
    for (int i = blockIdx.x * blockDim.x + threadIdx.x; i < n4; i += gridDim.x * blockDim.x) {
        float4 v = *(const float4*)(s + (size_t)i * 4);
        __half2* dd = (__half2*)(d + (size_t)i * 4);
        dd[0] = __floats2half2_rn(v.x, v.y);
        dd[1] = __floats2half2_rn(v.z, v.w);
    }
}

// ------------- transpose fp32 [512][1024] -> fp16 [1024][512] --------------------
__global__ void tr_f2h_kernel(const float* __restrict__ s0, const float* __restrict__ s1,
                              __half* __restrict__ d0, __half* __restrict__ d1)
{
    const float* src = blockIdx.z ? s1 : s0;
    __half* dst = blockIdx.z ? d1 : d0;
    __shared__ float t[32][33];
    int c0 = blockIdx.x * 32, r0 = blockIdx.y * 32;
    int tx = threadIdx.x, ty = threadIdx.y;   // 32 x 8
    #pragma unroll
    for (int i = 0; i < 4; i++)
        t[ty + i * 8][tx] = src[(size_t)(r0 + ty + i * 8) * D_INNER + c0 + tx];
    __syncthreads();
    #pragma unroll
    for (int i = 0; i < 4; i++)
        dst[(size_t)(c0 + ty + i * 8) * D_MODEL + r0 + tx] =
            __float2half_rn(t[tx][ty + i * 8]);
}

// ============ fp16 mma.sync GEMM: C = A[M,K] @ W[N,K]^T (+bias +resid) ==========
// CTA tile 128x128, BK=64, 3-stage cp.async, 8 warps (4m x 2n), warp tile 32x64.
// grid.z selects direction set; ksplit<K enables dual-A k-stitching.
#define GT_STAGES 3
#define GT_ASZ 16384
#define GT_STG (2 * GT_ASZ)
#define GT_SMEM (GT_STAGES * GT_STG + 1024)

__global__ void __launch_bounds__(256, 2)
gemm_f16(const __half* __restrict__ A0, const __half* __restrict__ A1, int lda,
         const __half* __restrict__ W0, const __half* __restrict__ W1, int Wld,
         void* C0v, void* C1v, int ldc, int ccolstep,
         int N, int K, int ksplit,
         int flipAmask, int flipCmask, int halfOut,
         const float* __restrict__ bias,
         const float* __restrict__ resid,
         const __half* __restrict__ residh,
         float* __restrict__ aux, int auxlo)
{
    extern __shared__ char dsm[];
    const uint32_t sb_raw = (uint32_t)__cvta_generic_to_shared(dsm);
    const uint32_t sb = (sb_raw + 1023u) & ~1023u;

    const int z = blockIdx.z;
    const int dual = (ksplit < K);
    const __half* Aa = dual ? A0 : (z ? A1 : A0);
    const __half* W = z ? W1 : W0;
    void* Cv = z ? C1v : C0v;
    const int ccol = z * ccolstep;
    const int flip_a = dual ? (flipAmask & 1) : ((flipAmask >> z) & 1);
    const int flip_b = (flipAmask >> 1) & 1;
    const int flipC = (flipCmask >> z) & 1;
    if (aux) aux += (size_t)z * AUXZ;

    const int tid = threadIdx.x;
    const int l   = tid & 31;
    const int w   = tid >> 5;
    const int wm  = w >> 1;
    const int wn  = w & 1;
    const int m0  = blockIdx.y * 128;
    const int n0  = blockIdx.x * 128;

    const int lr = l & 15;
    const int lc = l >> 4;
    const int lx = lr & 7;

    int arowA[4], arowB[4];
    #pragma unroll
    for (int i = 0; i < 4; i++) {
        int rr = (tid + i * 256) >> 3;
        int r = m0 + rr;
        arowA[i] = flip_a ? fliprow(r) : r;
        arowB[i] = flip_b ? fliprow(r) : r;
    }

    float acc[2][8][4];
    #pragma unroll
    for (int mi = 0; mi < 2; mi++)
        #pragma unroll
        for (int ni = 0; ni < 8; ni++)
            #pragma unroll
            for (int k = 0; k < 4; k++) acc[mi][ni][k] = 0.f;

    auto issue = [&](int s) {
        const int k0 = s * 64;
        const uint32_t base = sb + (s % GT_STAGES) * GT_STG;
        const __half* Ap = Aa;
        const int* ar = arowA;
        int kk = k0;
        if (dual && k0 >= ksplit) { Ap = A1; ar = arowB; kk = k0 - ksplit; }
        #pragma unroll
        for (int i = 0; i < 4; i++) {
            int q = tid + i * 256;
            int rr = q >> 3, ch = q & 7;
            int off = rr * 128 + ((ch ^ (rr & 7)) << 4);
            cpa16(base + off, Ap + (size_t)ar[i] * lda + kk + ch * 8, 16);
        }
        #pragma unroll
        for (int i = 0; i < 4; i++) {
            int q = tid + i * 256;
            int rr = q >> 3, ch = q & 7;
            int off = rr * 128 + ((ch ^ (rr & 7)) << 4);
            int n = n0 + rr;
            cpa16(base + GT_ASZ + off,
                  W + (size_t)(n < N ? n : 0) * Wld + k0 + ch * 8, (n < N) ? 16 : 0);
        }
    };
    auto compute = [&](int s) {
        const uint32_t Ab = sb + s * GT_STG;
        const uint32_t Bb = Ab + GT_ASZ;
        #pragma unroll
        for (int ks = 0; ks < 4; ks++) {
            const int chsel = ((ks << 1) | lc) ^ lx;
            uint32_t af[2][4];
            #pragma unroll
            for (int mi = 0; mi < 2; mi++) {
                uint32_t ad = Ab + (wm * 32 + mi * 16 + lr) * 128 + (chsel << 4);
                asm volatile("ldmatrix.sync.aligned.m8n8.x4.shared.b16 {%0,%1,%2,%3}, [%4];"
                    : "=r"(af[mi][0]), "=r"(af[mi][1]), "=r"(af[mi][2]), "=r"(af[mi][3])
                    : "r"(ad));
            }
            uint32_t bf[8][2];
            #pragma unroll
            for (int p = 0; p < 4; p++) {
                uint32_t bd = Bb + (wn * 64 + p * 16 + lr) * 128 + (chsel << 4);
                uint32_t q0, q1, q2, q3;
                asm volatile("ldmatrix.sync.aligned.m8n8.x4.shared.b16 {%0,%1,%2,%3}, [%4];"
                    : "=r"(q0), "=r"(q1), "=r"(q2), "=r"(q3) : "r"(bd));
                bf[2 * p][0] = q0;     bf[2 * p][1] = q2;
                bf[2 * p + 1][0] = q1; bf[2 * p + 1][1] = q3;
            }
            #pragma unroll
            for (int mi = 0; mi < 2; mi++)
                #pragma unroll
                for (int ni = 0; ni < 8; ni++) {
                    asm volatile(
                        "mma.sync.aligned.m16n8k16.row.col.f32.f16.f16.f32 "
                        "{%0,%1,%2,%3},{%4,%5,%6,%7},{%8,%9},{%0,%1,%2,%3};"
                        : "+f"(acc[mi][ni][0]), "+f"(acc[mi][ni][1]),
                          "+f"(acc[mi][ni][2]), "+f"(acc[mi][ni][3])
                        : "r"(af[mi][0]), "r"(af[mi][1]), "r"(af[mi][2]), "r"(af[mi][3]),
                          "r"(bf[ni][0]), "r"(bf[ni][1]));
                }
        }
    };

    const int KT = K / 64;
    issue(0); CP_COMMIT();
    issue(1); CP_COMMIT();
    for (int kt = 0; kt < KT; kt++) {
        CP_WAIT1();
        __syncthreads();
        if (kt + 2 < KT) issue(kt + 2);
        CP_COMMIT();
        compute(kt % GT_STAGES);
    }

    // epilogue
    #pragma unroll
    for (int mi = 0; mi < 2; mi++) {
        #pragma unroll
        for (int half = 0; half < 2; half++) {
            int r = m0 + wm * 32 + mi * 16 + (l >> 2) + half * 8;
            int cr = flipC ? fliprow(r) : r;
            const float* rp = resid + (size_t)cr * ldc + ccol;
            const __half* rh = residh + (size_t)cr * ldc + ccol;
            #pragma unroll
            for (int ni = 0; ni < 8; ni++) {
                int col = n0 + wn * 64 + ni * 8 + ((l & 3) << 1);
                if (col < N) {
                    float v0 = acc[mi][ni][half * 2 + 0];
                    float v1 = acc[mi][ni][half * 2 + 1];
                    if (bias)  { v0 += bias[col]; v1 += bias[col + 1]; }
                    if (residh) {
                        float2 rv = __half22float2(*(const __half2*)(rh + col));
                        v0 += rv.x; v1 += rv.y;
                    } else if (resid) {
                        v0 += rp[col]; v1 += rp[col + 1];
                    }
                    if (aux && col >= auxlo)
                        *(float2*)(aux + (size_t)cr * 16 + (col - auxlo)) =
                            make_float2(v0, v1);
                    if (halfOut) {
                        __half2* hp = (__half2*)((__half*)Cv + (size_t)cr * ldc + ccol + col);
                        *hp = __floats2half2_rn(v0, v1);
                    } else {
                        float* cp = (float*)Cv + (size_t)cr * ldc + ccol;
                        *(float2*)(cp + col) = make_float2(v0, v1);
                    }
                }
            }
        }
    }
}

// helper: silu
__device__ __forceinline__ float siluf(float v) { return v / (1.f + expf(-v)); }

// ======== fused conv + chunked scan pass A (local from zero) =====================
__global__ void __launch_bounds__(256)
scanA_kernel(const float* __restrict__ Al0, const float* __restrict__ Al1,
             const float* __restrict__ cw0, const float* __restrict__ cw1,
             const float* __restrict__ cb0, const float* __restrict__ cb1,
             const float* __restrict__ db0, const float* __restrict__ db1)
{
    const int c = blockIdx.x, h = blockIdx.y;
    const int b = blockIdx.z & (B_SZ - 1), dir = blockIdx.z >> 3;
    const int tid = threadIdx.x;
    const int p = tid >> 2, q = tid & 3;
    const float Aneg = -expf((dir ? Al1 : Al0)[h]);
    const float* conv_w  = dir ? cw1 : cw0;
    const float* conv_b  = dir ? cb1 : cb0;
    const float* dt_bias = dir ? db1 : db0;
    const __half* zx = g_zx16[dir];

    __shared__ float szx[CS + 3][80];
    __shared__ float sx[CS][64];
    __shared__ float sB[CS][16];
    __shared__ float sdt[CS];
    __shared__ float sdA[CS];
    __shared__ float scw[80 * 4];
    __shared__ float scb[80];

    const int l0 = c * CS;
    const size_t rowbase = (size_t)b * L_SEQ + l0;

    // vectorized half2 staging: 40 half2 per row cover 80 channels
    for (int idx = tid; idx < (CS + 3) * 40; idx += 256) {
        int s = idx / 40, ch2 = idx % 40;
        int ll = l0 + s - 3;
        int zc = (ch2 < 32) ? (D_INNER + h * 64 + 2 * ch2)
                            : (D_INNER + 1024 + (2 * ch2 - 64));
        float2 f = make_float2(0.f, 0.f);
        if (ll >= 0)
            f = __half22float2(*(const __half2*)&zx[((size_t)b * L_SEQ + ll) * D_IN_PROJ + zc]);
        szx[s][2 * ch2] = f.x;
        szx[s][2 * ch2 + 1] = f.y;
    }
    if (tid < 80) {
        int cc = (tid < 64) ? (h * 64 + tid) : (1024 + (tid - 64));
        scb[tid] = conv_b[cc];
        #pragma unroll
        for (int k = 0; k < 4; k++) scw[tid * 4 + k] = conv_w[cc * 4 + k];
    }
    if (tid < CS) {
        float raw = g_dtraw[dir][(rowbase + tid) * 16 + h] + dt_bias[h];
        float sp = (raw > 20.f) ? raw : log1pf(expf(raw));
        sdt[tid] = sp;
        sdA[tid] = expf(sp * Aneg);
    }
    __syncthreads();

    for (int idx = tid; idx < CS * 80; idx += 256) {
        int s = idx / 80, ch = idx % 80;
        float v = scb[ch];
        #pragma unroll
        for (int k = 0; k < 4; k++) v += szx[s + k][ch] * scw[ch * 4 + k];
        v = siluf(v);
        if (ch < 64) sx[s][ch] = v; else sB[s][ch - 64] = v;
    }
    __syncthreads();

    float h0 = 0.f, h1 = 0.f, h2 = 0.f, h3 = 0.f;
    #pragma unroll 4
    for (int s = 0; s < CS; s++) {
        float dA = sdA[s];
        float coef = sdt[s] * sx[s][p];
        float4 Bv = *(const float4*)&sB[s][q * 4];
        h0 = h0 * dA + coef * Bv.x;
        h1 = h1 * dA + coef * Bv.y;
        h2 = h2 * dA + coef * Bv.z;
        h3 = h3 * dA + coef * Bv.w;
    }
    size_t base = (((size_t)(b * NHEADS + h) * NC + c) << 10) + tid * 4;
    *(uint2*)&g_hstate[dir][base] = pack_h4(h0, h1, h2, h3);
    if (tid == 0) {
        float P = 1.f;
        for (int s = 0; s < CS; s++) P *= sdA[s];
        g_P[dir][(b * NHEADS + h) * NC + c] = P;
    }
}

// ======== chunked scan: middle combine (16-deep register prefetch ring) =========
#define MID_PF 16
__global__ void __launch_bounds__(256)
scanMid_kernel()
{
    const int h = blockIdx.x, b = blockIdx.y, dir = blockIdx.z;
    const int tid = threadIdx.x;
    __half* hs = g_hstate[dir];
    const size_t base = ((size_t)(b * NHEADS + h) * NC << 10) + tid * 4;
    __shared__ float sP[NC];
    if (tid < NC) sP[tid] = g_P[dir][(b * NHEADS + h) * NC + tid];
    __syncthreads();

    uint2 buf[MID_PF];
    #pragma unroll
    for (int i = 0; i < MID_PF; i++)
        buf[i] = *(const uint2*)&hs[base + ((size_t)i << 10)];

    float4 run = make_float4(0.f, 0.f, 0.f, 0.f);
    #pragma unroll
    for (int c = 0; c < NC; c++) {
        float4 endv = unpack_h4(buf[c % MID_PF]);
        if (c + MID_PF < NC)
            buf[c % MID_PF] = *(const uint2*)&hs[base + ((size_t)(c + MID_PF) << 10)];
        *(uint2*)&hs[base + ((size_t)c << 10)] = pack_h4(run.x, run.y, run.z, run.w);
        float P = sP[c];
        run.x = P * run.x + endv.x;
        run.y = P * run.y + endv.y;
        run.z = P * run.z + endv.z;
        run.w = P * run.w + endv.w;
    }
}

// ======== fused conv + chunked scan pass B (seeded, emit y fp16) =================
#define SB_SMEM ((67 * 96 + 64 * 64 + 1024 + 1024 + 64 + 64 + 384 + 96) * 4)

__global__ void __launch_bounds__(256)
scanB_kernel(const float* __restrict__ Al0, const float* __restrict__ Al1,
             const float* __restrict__ Dp0, const float* __restrict__ Dp1,
             const float* __restrict__ cw0, const float* __restrict__ cw1,
             const float* __restrict__ cb0, const float* __restrict__ cb1,
             const float* __restrict__ db0, const float* __restrict__ db1)
{
    extern __shared__ float sm[];
    float* szx = sm;                       // [67][96]
    float* sx  = sm + 67 * 96;             // [64][64]
    float* sB  = sx + 4096;                // [64][16]
    float* sC  = sB + 1024;                // [64][16]
    float* sdt = sC + 1024;                // [64]
    float* sdA = sdt + 64;                 // [64]
    float* scw = sdA + 64;                 // [96*4]
    float* scb = scw + 384;                // [96]
    float* sy  = szx;                      // reuse after conv phase

    const int c = blockIdx.x, h = blockIdx.y;
    const int b = blockIdx.z & (B_SZ - 1), dir = blockIdx.z >> 3;
    const int tid = threadIdx.x;
    const int p = tid >> 2, q = tid & 3;
    const float Aneg = -expf((dir ? Al1 : Al0)[h]);
    const float Dh = (dir ? Dp1 : Dp0)[h];
    const float* conv_w  = dir ? cw1 : cw0;
    const float* conv_b  = dir ? cb1 : cb0;
    const float* dt_bias = dir ? db1 : db0;
    const __half* zx = g_zx16[dir];

    const int l0 = c * CS;
    const size_t rowbase = (size_t)b * L_SEQ + l0;

    // vectorized half2 staging: 48 half2 per row cover 96 channels
    for (int idx = tid; idx < (CS + 3) * 48; idx += 256) {
        int s = idx / 48, ch2 = idx % 48;
        int ll = l0 + s - 3;
        int zc = (ch2 < 32) ? (D_INNER + h * 64 + 2 * ch2)
                            : (D_INNER + 1024 + (2 * ch2 - 64));
        float2 f = make_float2(0.f, 0.f);
        if (ll >= 0)
            f = __half22float2(*(const __half2*)&zx[((size_t)b * L_SEQ + ll) * D_IN_PROJ + zc]);
        szx[s * 96 + 2 * ch2] = f.x;
        szx[s * 96 + 2 * ch2 + 1] = f.y;
    }
    if (tid < 96) {
        int cc = (tid < 64) ? (h * 64 + tid) : (1024 + (tid - 64));
        scb[tid] = conv_b[cc];
        #pragma unroll
        for (int k = 0; k < 4; k++) scw[tid * 4 + k] = conv_w[cc * 4 + k];
    }
    if (tid < CS) {
        float raw = g_dtraw[dir][(rowbase + tid) * 16 + h] + dt_bias[h];
        float sp = (raw > 20.f) ? raw : log1pf(expf(raw));
        sdt[tid] = sp;
        sdA[tid] = expf(sp * Aneg);
    }
    float4 hin = unpack_h4(
        *(const uint2*)&g_hstate[dir][(((size_t)(b * NHEADS + h) * NC + c) << 10) + tid * 4]);
    __syncthreads();

    for (int idx = tid; idx < CS * 96; idx += 256) {
        int s = idx / 96, ch = idx % 96;
        float v = scb[ch];
        #pragma unroll
        for (int k = 0; k < 4; k++) v += szx[(s + k) * 96 + ch] * scw[ch * 4 + k];
        v = siluf(v);
        if (ch < 64) sx[s * 64 + ch] = v;
        else if (ch < 80) sB[s * 16 + (ch - 64)] = v;
        else sC[s * 16 + (ch - 80)] = v;
    }
    __syncthreads();

    float h0 = hin.x, h1 = hin.y, h2 = hin.z, h3 = hin.w;
    for (int s = 0; s < CS; s++) {
        float dA = sdA[s];
        float xv = sx[s * 64 + p];
        float coef = sdt[s] * xv;
        float4 Bv = *(const float4*)&sB[s * 16 + q * 4];
        float4 Cv = *(const float4*)&sC[s * 16 + q * 4];
        h0 = h0 * dA + coef * Bv.x;
        h1 = h1 * dA + coef * Bv.y;
        h2 = h2 * dA + coef * Bv.z;
        h3 = h3 * dA + coef * Bv.w;
        float yp = h0 * Cv.x + h1 * Cv.y + h2 * Cv.z + h3 * Cv.w;
        yp += __shfl_xor_sync(0xffffffffu, yp, 1);
        yp += __shfl_xor_sync(0xffffffffu, yp, 2);
        if (q == 0) sy[s * 64 + p] = yp + Dh * xv;
    }
    __syncthreads();
    // emit y as fp16 (pre-gating)
    for (int idx = tid; idx < CS * 32; idx += 256) {
        int s = idx >> 5, pp = (idx & 31) * 2;
        *(__half2*)&g_y16[dir][(rowbase + s) * D_INNER + h * 64 + pp] =
            __floats2half2_rn(sy[s * 64 + pp], sy[s * 64 + pp + 1]);
    }
}

// ------- y16 *= silu(z); RMSNorm * norm_w (in place; 128 thr, 16B loads) ---------
__global__ void gate_rms_kernel(const float* __restrict__ nw0, const float* __restrict__ nw1)
{
    const int row = blockIdx.x, dir = blockIdx.y, tid = threadIdx.x;  // 128 thr
    const float* norm_w = dir ? nw1 : nw0;
    uint4* yp4 = (uint4*)&g_y16[dir][(size_t)row * D_INNER + tid * 8];
    const uint4 zl = *(const uint4*)&g_zx16[dir][(size_t)row * D_IN_PROJ + tid * 8];
    uint4 yl = *yp4;
    float yv[8], zv[8];
    {
        const __half2* yh = (const __half2*)&yl;
        const __half2* zh = (const __half2*)&zl;
        #pragma unroll
        for (int i = 0; i < 4; i++) {
            float2 a = __half22float2(yh[i]);
            float2 b = __half22float2(zh[i]);
            yv[2 * i] = a.x; yv[2 * i + 1] = a.y;
            zv[2 * i] = b.x; zv[2 * i + 1] = b.y;
        }
    }
    float ss = 0.f;
    #pragma unroll
    for (int i = 0; i < 8; i++) {
        yv[i] *= siluf(zv[i]);
        ss += yv[i] * yv[i];
    }
    __shared__ float red[4];
    #pragma unroll
    for (int o = 16; o > 0; o >>= 1) ss += __shfl_xor_sync(0xffffffffu, ss, o);
    if ((tid & 31) == 0) red[tid >> 5] = ss;
    __syncthreads();
    float tot = red[0] + red[1] + red[2] + red[3];
    float sc = rsqrtf(tot * (1.f / D_INNER) + 1e-5f);
    float4 nv0 = *(const float4*)&norm_w[tid * 8];
    float4 nv1 = *(const float4*)&norm_w[tid * 8 + 4];
    __half2* yo = (__half2*)&yl;
    yo[0] = __floats2half2_rn(yv[0] * sc * nv0.x, yv[1] * sc * nv0.y);
    yo[1] = __floats2half2_rn(yv[2] * sc * nv0.z, yv[3] * sc * nv0.w);
    yo[2] = __floats2half2_rn(yv[4] * sc * nv1.x, yv[5] * sc * nv1.y);
    yo[3] = __floats2half2_rn(yv[6] * sc * nv1.z, yv[7] * sc * nv1.w);
    *yp4 = yl;
}

// ---------------- final LayerNorm over 512 (fp16 in) -> d_out --------------------
__global__ void ln_kernel(const float* __restrict__ ln_w, const float* __restrict__ ln_b,
                          float* __restrict__ out)
{
    const int row = blockIdx.x, tid = threadIdx.x;  // 128 threads
    const size_t base = (size_t)row * D_MODEL;
    const __half2* pp = (const __half2*)&g_pre16[base + tid * 4];
    float2 a = __half22float2(pp[0]);
    float2 bb = __half22float2(pp[1]);
    float4 v = make_float4(a.x, a.y, bb.x, bb.y);
    float s = v.x + v.y + v.z + v.w;
    float s2 = v.x * v.x + v.y * v.y + v.z * v.z + v.w * v.w;
    __shared__ float rs[4], rs2[4];
    #pragma unroll
    for (int o = 16; o > 0; o >>= 1) {
        s  += __shfl_xor_sync(0xffffffffu, s, o);
        s2 += __shfl_xor_sync(0xffffffffu, s2, o);
    }
    if ((tid & 31) == 0) { rs[tid >> 5] = s; rs2[tid >> 5] = s2; }
    __syncthreads();
    float ts = rs[0] + rs[1] + rs[2] + rs[3];
    float ts2 = rs2[0] + rs2[1] + rs2[2] + rs2[3];
    float mu = ts * (1.f / D_MODEL);
    float var = ts2 * (1.f / D_MODEL) - mu * mu;
    float isd = rsqrtf(var + 1e-5f);
    float4 wv = *(const float4*)&ln_w[tid * 4];
    float4 bv = *(const float4*)&ln_b[tid * 4];
    float4 o;
    o.x = (v.x - mu) * isd * wv.x + bv.x;
    o.y = (v.y - mu) * isd * wv.y + bv.y;
    o.z = (v.z - mu) * isd * wv.z + bv.z;
    o.w = (v.w - mu) * isd * wv.w + bv.w;
    *(float4*)&out[base + tid * 4] = o;
}

// ---------------- orchestration ---------------------------------------------------
extern "C" void kernel_launch(void* const* d_in, const int* in_sizes, int n_in,
                              void* d_out, int out_size)
{
    const float* x      = (const float*)d_in[0];
    const float* f_in_proj  = (const float*)d_in[1];
    const float* f_conv_w   = (const float*)d_in[2];
    const float* f_conv_b   = (const float*)d_in[3];
    const float* f_dt_bias  = (const float*)d_in[4];
    const float* f_A_log    = (const float*)d_in[5];
    const float* f_D        = (const float*)d_in[6];
    const float* f_norm_w   = (const float*)d_in[7];
    const float* f_out_proj = (const float*)d_in[8];
    const float* b_in_proj  = (const float*)d_in[9];
    const float* b_conv_w   = (const float*)d_in[10];
    const float* b_conv_b   = (const float*)d_in[11];
    const float* b_dt_bias  = (const float*)d_in[12];
    const float* b_A_log    = (const float*)d_in[13];
    const float* b_D        = (const float*)d_in[14];
    const float* b_norm_w   = (const float*)d_in[15];
    const float* b_out_proj = (const float*)d_in[16];
    const float* proj_w = (const float*)d_in[17];
    const float* proj_b = (const float*)d_in[18];
    const float* ln_w   = (const float*)d_in[19];
    const float* ln_b   = (const float*)d_in[20];

    float *dtraw;
    __half *zx16, *pre16, *x16, *wip16, *wpr16, *wofT16, *wcomb16, *y16;
    cudaGetSymbolAddress((void**)&zx16, g_zx16);
    cudaGetSymbolAddress((void**)&dtraw, g_dtraw);
    cudaGetSymbolAddress((void**)&pre16, g_pre16);
    cudaGetSymbolAddress((void**)&x16, g_x16);
    cudaGetSymbolAddress((void**)&wip16, g_wip16);
    cudaGetSymbolAddress((void**)&wpr16, g_wpr16);
    cudaGetSymbolAddress((void**)&wofT16, g_wofT16);
    cudaGetSymbolAddress((void**)&wcomb16, g_wcomb16);
    cudaGetSymbolAddress((void**)&y16, g_y16);

    cudaFuncSetAttribute(gemm_f16, cudaFuncAttributeMaxDynamicSharedMemorySize, GT_SMEM);
    cudaFuncSetAttribute(scanB_kernel, cudaFuncAttributeMaxDynamicSharedMemorySize, SB_SMEM);

    // fp32 -> fp16 conversions (x + all weights in ONE launch) + out_proj transposes
    f2h_multi_kernel<<<dim3(512, 4), 256>>>(
        f_in_proj, b_in_proj, proj_w, x,
        wip16, wip16 + (size_t)D_IN_PROJ * D_MODEL, wpr16, x16,
        D_IN_PROJ * D_MODEL / 4, D_IN_PROJ * D_MODEL / 4,
        D_MODEL * D_INNER / 4, BL * D_MODEL / 4);
    tr_f2h_kernel<<<dim3(32, 16, 2), dim3(32, 8)>>>(
        f_out_proj, b_out_proj, wofT16, wofT16 + (size_t)D_INNER * D_MODEL);

    // weight combine: wcomb[m][k + dir*1024] = proj_w[m][n + dir*512] * out_proj_dir[n][k]
    gemm_f16<<<dim3(D_INNER / 128, D_MODEL / 128, 2), 256, GT_SMEM>>>(
        wpr16, wpr16 + 512, D_INNER,
        wofT16, wofT16 + (size_t)D_INNER * D_MODEL, D_MODEL,
        wcomb16, wcomb16, 2 * D_INNER, D_INNER,
        D_INNER, D_MODEL, D_MODEL, 0, 0, 1, nullptr, nullptr, nullptr, nullptr, 0);

    // in_proj both dirs -> fp16 zx + fp32 dt aux
    gemm_f16<<<dim3((D_IN_PROJ + 127) / 128, BL / 128, 2), 256, GT_SMEM>>>(
        x16, x16, D_MODEL, wip16, wip16 + (size_t)D_IN_PROJ * D_MODEL, D_MODEL,
        zx16, zx16 + (size_t)BL * D_IN_PROJ, D_IN_PROJ, 0,
        D_IN_PROJ, D_MODEL, D_MODEL, 0b10, 0, 1, nullptr, nullptr, nullptr,
        dtraw, D_INNER + CONV_DIM);

    // fused conv + scan
    scanA_kernel<<<dim3(NC, NHEADS, 2 * B_SZ), 256>>>(
        f_A_log, b_A_log, f_conv_w, b_conv_w, f_conv_b, b_conv_b, f_dt_bias, b_dt_bias);
    scanMid_kernel<<<dim3(NHEADS, B_SZ, 2), 256>>>();
    scanB_kernel<<<dim3(NC, NHEADS, 2 * B_SZ), 256, SB_SMEM>>>(
        f_A_log, b_A_log, f_D, b_D,
        f_conv_w, b_conv_w, f_conv_b, b_conv_b, f_dt_bias, b_dt_bias);

    // gate + RMS normalization (in place on y16)
    gate_rms_kernel<<<dim3(BL, 2), 128>>>(f_norm_w, b_norm_w);

    // combined projection: pre16 = x16 + proj_b + [y_f | y_b(flip)] @ wcomb^T (K=2048)
    gemm_f16<<<dim3(D_MODEL / 128, BL / 128, 1), 256, GT_SMEM>>>(
        y16, y16 + (size_t)BL * D_INNER, D_INNER,
        wcomb16, wcomb16, 2 * D_INNER,
        pre16, pre16, D_MODEL, 0,
        D_MODEL, 2 * D_INNER, D_INNER, 0b10, 0, 1, proj_b, nullptr, x16,
        nullptr, 0);

    ln_kernel<<<BL, 128>>>(ln_w, ln_b, (float*)d_out);
}

// round 17
// speedup vs baseline: 1.4589x; 1.0788x over previous
#include <cuda_runtime.h>
#include <cuda_fp16.h>
#include <cstdint>

#define B_SZ    8
#define L_SEQ   4096
#define D_MODEL 512
#define D_INNER 1024
#define NHEADS  16
#define HEADDIM 64
#define D_STATE 16
#define CONV_DIM 1056
#define D_IN_PROJ 2096
#define BL      (B_SZ * L_SEQ)
#define CS      64
#define NC      (L_SEQ / CS)
#define AUXZ    ((size_t)BL * 16)

// ---------------- scratch (device globals; no allocation allowed) ----------------
__device__ __half g_zx16[2][(size_t)BL * D_IN_PROJ];   // in_proj out (fp16)
__device__ float g_dtraw[2][(size_t)BL * 16];          // dt pre-softplus (fp32)
__device__ __half g_pre16[(size_t)BL * D_MODEL];       // pre-layernorm (fp16)
__device__ __half g_hstate[2][(size_t)B_SZ * NHEADS * NC * 1024];  // fp16 seeds
__device__ float g_P[2][B_SZ * NHEADS * NC];
__device__ __half g_xc[2][(size_t)BL * D_INNER];       // conv+silu x (fp16, per-head)
__device__ __half g_bc[2][(size_t)BL * 32];            // conv+silu B|C (fp16)

__device__ __half g_x16[(size_t)BL * D_MODEL];
__device__ __half g_wip16[2][(size_t)D_IN_PROJ * D_MODEL];
__device__ __half g_wpr16[(size_t)D_MODEL * D_INNER];
__device__ __half g_wofT16[2][(size_t)D_INNER * D_MODEL]; // out_proj^T fp16
__device__ __half g_wcomb16[(size_t)D_MODEL * 2 * D_INNER]; // [512][2048]
__device__ __half g_y16[2][(size_t)BL * D_INNER];      // y (pre-gate) -> gated/normed

__device__ __forceinline__ int fliprow(int r) {
    return (r & ~(L_SEQ - 1)) | ((L_SEQ - 1) - (r & (L_SEQ - 1)));
}
__device__ __forceinline__ void cpa16(uint32_t dst, const void* src, int sz) {
    asm volatile("cp.async.cg.shared.global [%0], [%1], 16, %2;"
                 :: "r"(dst), "l"(src), "r"(sz));
}
#define CP_COMMIT() asm volatile("cp.async.commit_group;" ::: "memory")
#define CP_WAIT1()  asm volatile("cp.async.wait_group 1;" ::: "memory")

__device__ __forceinline__ uint2 pack_h4(float a, float b, float c, float d) {
    uint2 r;
    __half2 h0 = __floats2half2_rn(a, b);
    __half2 h1 = __floats2half2_rn(c, d);
    r.x = *(uint32_t*)&h0;
    r.y = *(uint32_t*)&h1;
    return r;
}
__device__ __forceinline__ float4 unpack_h4(uint2 v) {
    __half2 h0 = *(__half2*)&v.x;
    __half2 h1 = *(__half2*)&v.y;
    float2 a = __half22float2(h0);
    float2 b = __half22float2(h1);
    return make_float4(a.x, a.y, b.x, b.y);
}

// ---------------- merged 4-segment fp32 -> fp16 convert --------------------------
__global__ void f2h_multi_kernel(const float* __restrict__ s0, const float* __restrict__ s1,
                                 const float* __restrict__ s2, const float* __restrict__ s3,
                                 __half* __restrict__ d0, __half* __restrict__ d1,
                                 __half* __restrict__ d2, __half* __restrict__ d3,
                                 int n0, int n1, int n2, int n3)
{
    const float* s;
    __half* d;
    int n4;
    switch (blockIdx.y) {
        case 0: s = s0; d = d0; n4 = n0; break;
        case 1: s = s1; d = d1; n4 = n1; break;
        case 2: s = s2; d = d2; n4 = n2; break;
        default: s = s3; d = d3; n4 = n3; break;
    }
    for (int i = blockIdx.x * blockDim.x + threadIdx.x; i < n4; i += gridDim.x * blockDim.x) {
        float4 v = *(const float4*)(s + (size_t)i * 4);
        __half2* dd = (__half2*)(d + (size_t)i * 4);
        dd[0] = __floats2half2_rn(v.x, v.y);
        dd[1] = __floats2half2_rn(v.z, v.w);
    }
}

// ------------- transpose fp32 [512][1024] -> fp16 [1024][512] --------------------
__global__ void tr_f2h_kernel(const float* __restrict__ s0, const float* __restrict__ s1,
                              __half* __restrict__ d0, __half* __restrict__ d1)
{
    const float* src = blockIdx.z ? s1 : s0;
    __half* dst = blockIdx.z ? d1 : d0;
    __shared__ float t[32][33];
    int c0 = blockIdx.x * 32, r0 = blockIdx.y * 32;
    int tx = threadIdx.x, ty = threadIdx.y;   // 32 x 8
    #pragma unroll
    for (int i = 0; i < 4; i++)
        t[ty + i * 8][tx] = src[(size_t)(r0 + ty + i * 8) * D_INNER + c0 + tx];
    __syncthreads();
    #pragma unroll
    for (int i = 0; i < 4; i++)
        dst[(size_t)(c0 + ty + i * 8) * D_MODEL + r0 + tx] =
            __float2half_rn(t[tx][ty + i * 8]);
}

// ============ fp16 mma.sync GEMM: C = A[M,K] @ W[N,K]^T (+bias +resid) ==========
#define GT_STAGES 3
#define GT_ASZ 16384
#define GT_STG (2 * GT_ASZ)
#define GT_SMEM (GT_STAGES * GT_STG + 1024)

__global__ void __launch_bounds__(256, 2)
gemm_f16(const __half* __restrict__ A0, const __half* __restrict__ A1, int lda,
         const __half* __restrict__ W0, const __half* __restrict__ W1, int Wld,
         void* C0v, void* C1v, int ldc, int ccolstep,
         int N, int K, int ksplit,
         int flipAmask, int flipCmask, int halfOut,
         const float* __restrict__ bias,
         const float* __restrict__ resid,
         const __half* __restrict__ residh,
         float* __restrict__ aux, int auxlo)
{
    extern __shared__ char dsm[];
    const uint32_t sb_raw = (uint32_t)__cvta_generic_to_shared(dsm);
    const uint32_t sb = (sb_raw + 1023u) & ~1023u;

    const int z = blockIdx.z;
    const int dual = (ksplit < K);
    const __half* Aa = dual ? A0 : (z ? A1 : A0);
    const __half* W = z ? W1 : W0;
    void* Cv = z ? C1v : C0v;
    const int ccol = z * ccolstep;
    const int flip_a = dual ? (flipAmask & 1) : ((flipAmask >> z) & 1);
    const int flip_b = (flipAmask >> 1) & 1;
    const int flipC = (flipCmask >> z) & 1;
    if (aux) aux += (size_t)z * AUXZ;

    const int tid = threadIdx.x;
    const int l   = tid & 31;
    const int w   = tid >> 5;
    const int wm  = w >> 1;
    const int wn  = w & 1;
    const int m0  = blockIdx.y * 128;
    const int n0  = blockIdx.x * 128;

    const int lr = l & 15;
    const int lc = l >> 4;
    const int lx = lr & 7;

    int arowA[4], arowB[4];
    #pragma unroll
    for (int i = 0; i < 4; i++) {
        int rr = (tid + i * 256) >> 3;
        int r = m0 + rr;
        arowA[i] = flip_a ? fliprow(r) : r;
        arowB[i] = flip_b ? fliprow(r) : r;
    }

    float acc[2][8][4];
    #pragma unroll
    for (int mi = 0; mi < 2; mi++)
        #pragma unroll
        for (int ni = 0; ni < 8; ni++)
            #pragma unroll
            for (int k = 0; k < 4; k++) acc[mi][ni][k] = 0.f;

    auto issue = [&](int s) {
        const int k0 = s * 64;
        const uint32_t base = sb + (s % GT_STAGES) * GT_STG;
        const __half* Ap = Aa;
        const int* ar = arowA;
        int kk = k0;
        if (dual && k0 >= ksplit) { Ap = A1; ar = arowB; kk = k0 - ksplit; }
        #pragma unroll
        for (int i = 0; i < 4; i++) {
            int q = tid + i * 256;
            int rr = q >> 3, ch = q & 7;
            int off = rr * 128 + ((ch ^ (rr & 7)) << 4);
            cpa16(base + off, Ap + (size_t)ar[i] * lda + kk + ch * 8, 16);
        }
        #pragma unroll
        for (int i = 0; i < 4; i++) {
            int q = tid + i * 256;
            int rr = q >> 3, ch = q & 7;
            int off = rr * 128 + ((ch ^ (rr & 7)) << 4);
            int n = n0 + rr;
            cpa16(base + GT_ASZ + off,
                  W + (size_t)(n < N ? n : 0) * Wld + k0 + ch * 8, (n < N) ? 16 : 0);
        }
    };
    auto compute = [&](int s) {
        const uint32_t Ab = sb + s * GT_STG;
        const uint32_t Bb = Ab + GT_ASZ;
        #pragma unroll
        for (int ks = 0; ks < 4; ks++) {
            const int chsel = ((ks << 1) | lc) ^ lx;
            uint32_t af[2][4];
            #pragma unroll
            for (int mi = 0; mi < 2; mi++) {
                uint32_t ad = Ab + (wm * 32 + mi * 16 + lr) * 128 + (chsel << 4);
                asm volatile("ldmatrix.sync.aligned.m8n8.x4.shared.b16 {%0,%1,%2,%3}, [%4];"
                    : "=r"(af[mi][0]), "=r"(af[mi][1]), "=r"(af[mi][2]), "=r"(af[mi][3])
                    : "r"(ad));
            }
            uint32_t bf[8][2];
            #pragma unroll
            for (int p = 0; p < 4; p++) {
                uint32_t bd = Bb + (wn * 64 + p * 16 + lr) * 128 + (chsel << 4);
                uint32_t q0, q1, q2, q3;
                asm volatile("ldmatrix.sync.aligned.m8n8.x4.shared.b16 {%0,%1,%2,%3}, [%4];"
                    : "=r"(q0), "=r"(q1), "=r"(q2), "=r"(q3) : "r"(bd));
                bf[2 * p][0] = q0;     bf[2 * p][1] = q2;
                bf[2 * p + 1][0] = q1; bf[2 * p + 1][1] = q3;
            }
            #pragma unroll
            for (int mi = 0; mi < 2; mi++)
                #pragma unroll
                for (int ni = 0; ni < 8; ni++) {
                    asm volatile(
                        "mma.sync.aligned.m16n8k16.row.col.f32.f16.f16.f32 "
                        "{%0,%1,%2,%3},{%4,%5,%6,%7},{%8,%9},{%0,%1,%2,%3};"
                        : "+f"(acc[mi][ni][0]), "+f"(acc[mi][ni][1]),
                          "+f"(acc[mi][ni][2]), "+f"(acc[mi][ni][3])
                        : "r"(af[mi][0]), "r"(af[mi][1]), "r"(af[mi][2]), "r"(af[mi][3]),
                          "r"(bf[ni][0]), "r"(bf[ni][1]));
                }
        }
    };

    const int KT = K / 64;
    issue(0); CP_COMMIT();
    issue(1); CP_COMMIT();
    for (int kt = 0; kt < KT; kt++) {
        CP_WAIT1();
        __syncthreads();
        if (kt + 2 < KT) issue(kt + 2);
        CP_COMMIT();
        compute(kt % GT_STAGES);
    }

    // epilogue
    #pragma unroll
    for (int mi = 0; mi < 2; mi++) {
        #pragma unroll
        for (int half = 0; half < 2; half++) {
            int r = m0 + wm * 32 + mi * 16 + (l >> 2) + half * 8;
            int cr = flipC ? fliprow(r) : r;
            const float* rp = resid + (size_t)cr * ldc + ccol;
            const __half* rh = residh + (size_t)cr * ldc + ccol;
            #pragma unroll
            for (int ni = 0; ni < 8; ni++) {
                int col = n0 + wn * 64 + ni * 8 + ((l & 3) << 1);
                if (col < N) {
                    float v0 = acc[mi][ni][half * 2 + 0];
                    float v1 = acc[mi][ni][half * 2 + 1];
                    if (bias)  { v0 += bias[col]; v1 += bias[col + 1]; }
                    if (residh) {
                        float2 rv = __half22float2(*(const __half2*)(rh + col));
                        v0 += rv.x; v1 += rv.y;
                    } else if (resid) {
                        v0 += rp[col]; v1 += rp[col + 1];
                    }
                    if (aux && col >= auxlo)
                        *(float2*)(aux + (size_t)cr * 16 + (col - auxlo)) =
                            make_float2(v0, v1);
                    if (halfOut) {
                        __half2* hp = (__half2*)((__half*)Cv + (size_t)cr * ldc + ccol + col);
                        *hp = __floats2half2_rn(v0, v1);
                    } else {
                        float* cp = (float*)Cv + (size_t)cr * ldc + ccol;
                        *(float2*)(cp + col) = make_float2(v0, v1);
                    }
                }
            }
        }
    }
}

// helper: silu
__device__ __forceinline__ float siluf(float v) { return v / (1.f + expf(-v)); }

// ======== fused conv(96ch) + scan pass A; writes per-head x + shared BC =========
__global__ void __launch_bounds__(256)
scanA_kernel(const float* __restrict__ Al0, const float* __restrict__ Al1,
             const float* __restrict__ cw0, const float* __restrict__ cw1,
             const float* __restrict__ cb0, const float* __restrict__ cb1,
             const float* __restrict__ db0, const float* __restrict__ db1)
{
    __shared__ float szx[(CS + 3) * 96];
    __shared__ float sdt[CS];
    __shared__ float sdA[CS];
    __shared__ float scw[96 * 4];
    __shared__ float scb[96];

    const int c = blockIdx.x, h = blockIdx.y;
    const int b = blockIdx.z & (B_SZ - 1), dir = blockIdx.z >> 3;
    const int tid = threadIdx.x;
    const int p = tid >> 2, q = tid & 3;
    const float Aneg = -expf((dir ? Al1 : Al0)[h]);
    const float* conv_w  = dir ? cw1 : cw0;
    const float* conv_b  = dir ? cb1 : cb0;
    const float* dt_bias = dir ? db1 : db0;
    const __half* zx = g_zx16[dir];
    __half* xc = g_xc[dir];
    __half* bc = g_bc[dir];

    const int l0 = c * CS;
    const size_t rowbase = (size_t)b * L_SEQ + l0;

    // stage zx halo: (CS+3) rows x 96 channels via half2
    for (int idx = tid; idx < (CS + 3) * 48; idx += 256) {
        int s = idx / 48, ch2 = idx % 48;
        int ll = l0 + s - 3;
        int zc = (ch2 < 32) ? (D_INNER + h * 64 + 2 * ch2)
                            : (D_INNER + 1024 + (2 * ch2 - 64));
        float2 f = make_float2(0.f, 0.f);
        if (ll >= 0)
            f = __half22float2(*(const __half2*)&zx[((size_t)b * L_SEQ + ll) * D_IN_PROJ + zc]);
        szx[s * 96 + 2 * ch2] = f.x;
        szx[s * 96 + 2 * ch2 + 1] = f.y;
    }
    if (tid < 96) {
        int cc = (tid < 64) ? (h * 64 + tid) : (1024 + (tid - 64));
        scb[tid] = conv_b[cc];
        #pragma unroll
        for (int k = 0; k < 4; k++) scw[tid * 4 + k] = conv_w[cc * 4 + k];
    }
    if (tid < CS) {
        float raw = g_dtraw[dir][(rowbase + tid) * 16 + h] + dt_bias[h];
        float sp = (raw > 20.f) ? raw : log1pf(expf(raw));
        sdt[tid] = sp;
        sdA[tid] = expf(sp * Aneg);
    }
    __syncthreads();

    // phase 1: conv+silu into registers; emit fp16 to per-head x / shared BC
    float cv[24];
    #pragma unroll
    for (int j = 0; j < 12; j++) {
        int idx2 = tid + j * 256;           // 0 .. CS*48-1
        int s = idx2 / 48, ch2 = idx2 % 48;
        int ch = 2 * ch2;
        float v0 = scb[ch], v1 = scb[ch + 1];
        #pragma unroll
        for (int k = 0; k < 4; k++) {
            v0 += szx[(s + k) * 96 + ch] * scw[ch * 4 + k];
            v1 += szx[(s + k) * 96 + ch + 1] * scw[(ch + 1) * 4 + k];
        }
        v0 = siluf(v0);
        v1 = siluf(v1);
        cv[2 * j] = v0;
        cv[2 * j + 1] = v1;
        __half2 hv = __floats2half2_rn(v0, v1);
        if (ch < 64)
            *(__half2*)&xc[(rowbase + s) * D_INNER + h * 64 + ch] = hv;
        else if (h == 0)
            *(__half2*)&bc[(rowbase + s) * 32 + (ch - 64)] = hv;
    }
    __syncthreads();
    // phase 2: write conv results back into szx as compact [CS][96]
    #pragma unroll
    for (int j = 0; j < 12; j++) {
        int idx2 = tid + j * 256;
        int s = idx2 / 48, ch2 = idx2 % 48;
        szx[s * 96 + 2 * ch2] = cv[2 * j];
        szx[s * 96 + 2 * ch2 + 1] = cv[2 * j + 1];
    }
    __syncthreads();

    float h0 = 0.f, h1 = 0.f, h2 = 0.f, h3 = 0.f;
    #pragma unroll 4
    for (int s = 0; s < CS; s++) {
        float dA = sdA[s];
        float coef = sdt[s] * szx[s * 96 + p];
        float4 Bv = *(const float4*)&szx[s * 96 + 64 + q * 4];
        h0 = h0 * dA + coef * Bv.x;
        h1 = h1 * dA + coef * Bv.y;
        h2 = h2 * dA + coef * Bv.z;
        h3 = h3 * dA + coef * Bv.w;
    }
    size_t base = (((size_t)(b * NHEADS + h) * NC + c) << 10) + tid * 4;
    *(uint2*)&g_hstate[dir][base] = pack_h4(h0, h1, h2, h3);
    if (tid == 0) {
        float P = 1.f;
        for (int s = 0; s < CS; s++) P *= sdA[s];
        g_P[dir][(b * NHEADS + h) * NC + c] = P;
    }
}

// ======== chunked scan: middle combine (16-deep register prefetch ring) =========
#define MID_PF 16
__global__ void __launch_bounds__(256)
scanMid_kernel()
{
    const int h = blockIdx.x, b = blockIdx.y, dir = blockIdx.z;
    const int tid = threadIdx.x;
    __half* hs = g_hstate[dir];
    const size_t base = ((size_t)(b * NHEADS + h) * NC << 10) + tid * 4;
    __shared__ float sP[NC];
    if (tid < NC) sP[tid] = g_P[dir][(b * NHEADS + h) * NC + tid];
    __syncthreads();

    uint2 buf[MID_PF];
    #pragma unroll
    for (int i = 0; i < MID_PF; i++)
        buf[i] = *(const uint2*)&hs[base + ((size_t)i << 10)];

    float4 run = make_float4(0.f, 0.f, 0.f, 0.f);
    #pragma unroll
    for (int c = 0; c < NC; c++) {
        float4 endv = unpack_h4(buf[c % MID_PF]);
        if (c + MID_PF < NC)
            buf[c % MID_PF] = *(const uint2*)&hs[base + ((size_t)(c + MID_PF) << 10)];
        *(uint2*)&hs[base + ((size_t)c << 10)] = pack_h4(run.x, run.y, run.z, run.w);
        float P = sP[c];
        run.x = P * run.x + endv.x;
        run.y = P * run.y + endv.y;
        run.z = P * run.z + endv.z;
        run.w = P * run.w + endv.w;
    }
}

// ======== scan pass B: reads per-head x + shared BC, seeded, emits y fp16 =======
__global__ void __launch_bounds__(256)
scanB_kernel(const float* __restrict__ Al0, const float* __restrict__ Al1,
             const float* __restrict__ Dp0, const float* __restrict__ Dp1,
             const float* __restrict__ db0, const float* __restrict__ db1)
{
    __shared__ float sxbc[CS * 96];
    __shared__ float sdt[CS];
    __shared__ float sdA[CS];

    const int c = blockIdx.x, h = blockIdx.y;
    const int b = blockIdx.z & (B_SZ - 1), dir = blockIdx.z >> 3;
    const int tid = threadIdx.x;
    const int p = tid >> 2, q = tid & 3;
    const float Aneg = -expf((dir ? Al1 : Al0)[h]);
    const float Dh = (dir ? Dp1 : Dp0)[h];
    const float* dt_bias = dir ? db1 : db0;
    const __half* xc = g_xc[dir];
    const __half* bc = g_bc[dir];

    const int l0 = c * CS;
    const size_t rowbase = (size_t)b * L_SEQ + l0;

    // stage per-head x (128B rows) -> sxbc[.., 0..63]
    for (int idx = tid; idx < CS * 32; idx += 256) {
        int s = idx >> 5, ch2 = idx & 31;
        float2 f = __half22float2(
            *(const __half2*)&xc[(rowbase + s) * D_INNER + h * 64 + 2 * ch2]);
        sxbc[s * 96 + 2 * ch2] = f.x;
        sxbc[s * 96 + 2 * ch2 + 1] = f.y;
    }
    // stage shared BC (64B rows) -> sxbc[.., 64..95]
    for (int idx = tid; idx < CS * 16; idx += 256) {
        int s = idx >> 4, ch2 = idx & 15;
        float2 f = __half22float2(*(const __half2*)&bc[(rowbase + s) * 32 + 2 * ch2]);
        sxbc[s * 96 + 64 + 2 * ch2] = f.x;
        sxbc[s * 96 + 64 + 2 * ch2 + 1] = f.y;
    }
    if (tid < CS) {
        float raw = g_dtraw[dir][(rowbase + tid) * 16 + h] + dt_bias[h];
        float sp = (raw > 20.f) ? raw : log1pf(expf(raw));
        sdt[tid] = sp;
        sdA[tid] = expf(sp * Aneg);
    }
    float4 hin = unpack_h4(
        *(const uint2*)&g_hstate[dir][(((size_t)(b * NHEADS + h) * NC + c) << 10) + tid * 4]);
    __syncthreads();

    float h0 = hin.x, h1 = hin.y, h2 = hin.z, h3 = hin.w;
    for (int s = 0; s < CS; s++) {
        float dA = sdA[s];
        float xv = sxbc[s * 96 + p];
        float coef = sdt[s] * xv;
        float4 Bv = *(const float4*)&sxbc[s * 96 + 64 + q * 4];
        float4 Cv = *(const float4*)&sxbc[s * 96 + 80 + q * 4];
        h0 = h0 * dA + coef * Bv.x;
        h1 = h1 * dA + coef * Bv.y;
        h2 = h2 * dA + coef * Bv.z;
        h3 = h3 * dA + coef * Bv.w;
        float yp = h0 * Cv.x + h1 * Cv.y + h2 * Cv.z + h3 * Cv.w;
        yp += __shfl_xor_sync(0xffffffffu, yp, 1);
        yp += __shfl_xor_sync(0xffffffffu, yp, 2);
        // shuffles warp-synchronize: all quad reads of sxbc[s*96+p] precede write
        if (q == 0) sxbc[s * 96 + p] = yp + Dh * xv;
    }
    __syncthreads();
    // emit y as fp16 (pre-gating) from reused x slots
    for (int idx = tid; idx < CS * 32; idx += 256) {
        int s = idx >> 5, pp = (idx & 31) * 2;
        *(__half2*)&g_y16[dir][(rowbase + s) * D_INNER + h * 64 + pp] =
            __floats2half2_rn(sxbc[s * 96 + pp], sxbc[s * 96 + pp + 1]);
    }
}

// ------- y16 *= silu(z); RMSNorm * norm_w (in place; 128 thr, 16B loads) ---------
__global__ void gate_rms_kernel(const float* __restrict__ nw0, const float* __restrict__ nw1)
{
    const int row = blockIdx.x, dir = blockIdx.y, tid = threadIdx.x;  // 128 thr
    const float* norm_w = dir ? nw1 : nw0;
    uint4* yp4 = (uint4*)&g_y16[dir][(size_t)row * D_INNER + tid * 8];
    const uint4 zl = *(const uint4*)&g_zx16[dir][(size_t)row * D_IN_PROJ + tid * 8];
    uint4 yl = *yp4;
    float yv[8], zv[8];
    {
        const __half2* yh = (const __half2*)&yl;
        const __half2* zh = (const __half2*)&zl;
        #pragma unroll
        for (int i = 0; i < 4; i++) {
            float2 a = __half22float2(yh[i]);
            float2 b = __half22float2(zh[i]);
            yv[2 * i] = a.x; yv[2 * i + 1] = a.y;
            zv[2 * i] = b.x; zv[2 * i + 1] = b.y;
        }
    }
    float ss = 0.f;
    #pragma unroll
    for (int i = 0; i < 8; i++) {
        yv[i] *= siluf(zv[i]);
        ss += yv[i] * yv[i];
    }
    __shared__ float red[4];
    #pragma unroll
    for (int o = 16; o > 0; o >>= 1) ss += __shfl_xor_sync(0xffffffffu, ss, o);
    if ((tid & 31) == 0) red[tid >> 5] = ss;
    __syncthreads();
    float tot = red[0] + red[1] + red[2] + red[3];
    float sc = rsqrtf(tot * (1.f / D_INNER) + 1e-5f);
    float4 nv0 = *(const float4*)&norm_w[tid * 8];
    float4 nv1 = *(const float4*)&norm_w[tid * 8 + 4];
    __half2* yo = (__half2*)&yl;
    yo[0] = __floats2half2_rn(yv[0] * sc * nv0.x, yv[1] * sc * nv0.y);
    yo[1] = __floats2half2_rn(yv[2] * sc * nv0.z, yv[3] * sc * nv0.w);
    yo[2] = __floats2half2_rn(yv[4] * sc * nv1.x, yv[5] * sc * nv1.y);
    yo[3] = __floats2half2_rn(yv[6] * sc * nv1.z, yv[7] * sc * nv1.w);
    *yp4 = yl;
}

// ---------------- final LayerNorm over 512 (fp16 in) -> d_out --------------------
__global__ void ln_kernel(const float* __restrict__ ln_w, const float* __restrict__ ln_b,
                          float* __restrict__ out)
{
    const int row = blockIdx.x, tid = threadIdx.x;  // 128 threads
    const size_t base = (size_t)row * D_MODEL;
    const __half2* pp = (const __half2*)&g_pre16[base + tid * 4];
    float2 a = __half22float2(pp[0]);
    float2 bb = __half22float2(pp[1]);
    float4 v = make_float4(a.x, a.y, bb.x, bb.y);
    float s = v.x + v.y + v.z + v.w;
    float s2 = v.x * v.x + v.y * v.y + v.z * v.z + v.w * v.w;
    __shared__ float rs[4], rs2[4];
    #pragma unroll
    for (int o = 16; o > 0; o >>= 1) {
        s  += __shfl_xor_sync(0xffffffffu, s, o);
        s2 += __shfl_xor_sync(0xffffffffu, s2, o);
    }
    if ((tid & 31) == 0) { rs[tid >> 5] = s; rs2[tid >> 5] = s2; }
    __syncthreads();
    float ts = rs[0] + rs[1] + rs[2] + rs[3];
    float ts2 = rs2[0] + rs2[1] + rs2[2] + rs2[3];
    float mu = ts * (1.f / D_MODEL);
    float var = ts2 * (1.f / D_MODEL) - mu * mu;
    float isd = rsqrtf(var + 1e-5f);
    float4 wv = *(const float4*)&ln_w[tid * 4];
    float4 bv = *(const float4*)&ln_b[tid * 4];
    float4 o;
    o.x = (v.x - mu) * isd * wv.x + bv.x;
    o.y = (v.y - mu) * isd * wv.y + bv.y;
    o.z = (v.z - mu) * isd * wv.z + bv.z;
    o.w = (v.w - mu) * isd * wv.w + bv.w;
    *(float4*)&out[base + tid * 4] = o;
}

// ---------------- orchestration ---------------------------------------------------
extern "C" void kernel_launch(void* const* d_in, const int* in_sizes, int n_in,
                              void* d_out, int out_size)
{
    const float* x      = (const float*)d_in[0];
    const float* f_in_proj  = (const float*)d_in[1];
    const float* f_conv_w   = (const float*)d_in[2];
    const float* f_conv_b   = (const float*)d_in[3];
    const float* f_dt_bias  = (const float*)d_in[4];
    const float* f_A_log    = (const float*)d_in[5];
    const float* f_D        = (const float*)d_in[6];
    const float* f_norm_w   = (const float*)d_in[7];
    const float* f_out_proj = (const float*)d_in[8];
    const float* b_in_proj  = (const float*)d_in[9];
    const float* b_conv_w   = (const float*)d_in[10];
    const float* b_conv_b   = (const float*)d_in[11];
    const float* b_dt_bias  = (const float*)d_in[12];
    const float* b_A_log    = (const float*)d_in[13];
    const float* b_D        = (const float*)d_in[14];
    const float* b_norm_w   = (const float*)d_in[15];
    const float* b_out_proj = (const float*)d_in[16];
    const float* proj_w = (const float*)d_in[17];
    const float* proj_b = (const float*)d_in[18];
    const float* ln_w   = (const float*)d_in[19];
    const float* ln_b   = (const float*)d_in[20];

    float *dtraw;
    __half *zx16, *pre16, *x16, *wip16, *wpr16, *wofT16, *wcomb16, *y16;
    cudaGetSymbolAddress((void**)&zx16, g_zx16);
    cudaGetSymbolAddress((void**)&dtraw, g_dtraw);
    cudaGetSymbolAddress((void**)&pre16, g_pre16);
    cudaGetSymbolAddress((void**)&x16, g_x16);
    cudaGetSymbolAddress((void**)&wip16, g_wip16);
    cudaGetSymbolAddress((void**)&wpr16, g_wpr16);
    cudaGetSymbolAddress((void**)&wofT16, g_wofT16);
    cudaGetSymbolAddress((void**)&wcomb16, g_wcomb16);
    cudaGetSymbolAddress((void**)&y16, g_y16);

    cudaFuncSetAttribute(gemm_f16, cudaFuncAttributeMaxDynamicSharedMemorySize, GT_SMEM);

    // fp32 -> fp16 conversions (x + all weights in ONE launch) + out_proj transposes
    f2h_multi_kernel<<<dim3(512, 4), 256>>>(
        f_in_proj, b_in_proj, proj_w, x,
        wip16, wip16 + (size_t)D_IN_PROJ * D_MODEL, wpr16, x16,
        D_IN_PROJ * D_MODEL / 4, D_IN_PROJ * D_MODEL / 4,
        D_MODEL * D_INNER / 4, BL * D_MODEL / 4);
    tr_f2h_kernel<<<dim3(32, 16, 2), dim3(32, 8)>>>(
        f_out_proj, b_out_proj, wofT16, wofT16 + (size_t)D_INNER * D_MODEL);

    // weight combine: wcomb[m][k + dir*1024] = proj_w[m][n + dir*512] * out_proj_dir[n][k]
    gemm_f16<<<dim3(D_INNER / 128, D_MODEL / 128, 2), 256, GT_SMEM>>>(
        wpr16, wpr16 + 512, D_INNER,
        wofT16, wofT16 + (size_t)D_INNER * D_MODEL, D_MODEL,
        wcomb16, wcomb16, 2 * D_INNER, D_INNER,
        D_INNER, D_MODEL, D_MODEL, 0, 0, 1, nullptr, nullptr, nullptr, nullptr, 0);

    // in_proj both dirs -> fp16 zx + fp32 dt aux
    gemm_f16<<<dim3((D_IN_PROJ + 127) / 128, BL / 128, 2), 256, GT_SMEM>>>(
        x16, x16, D_MODEL, wip16, wip16 + (size_t)D_IN_PROJ * D_MODEL, D_MODEL,
        zx16, zx16 + (size_t)BL * D_IN_PROJ, D_IN_PROJ, 0,
        D_IN_PROJ, D_MODEL, D_MODEL, 0b10, 0, 1, nullptr, nullptr, nullptr,
        dtraw, D_INNER + CONV_DIM);

    // fused conv(96ch) + scan A (emits per-head x + shared BC), mid, scan B
    scanA_kernel<<<dim3(NC, NHEADS, 2 * B_SZ), 256>>>(
        f_A_log, b_A_log, f_conv_w, b_conv_w, f_conv_b, b_conv_b, f_dt_bias, b_dt_bias);
    scanMid_kernel<<<dim3(NHEADS, B_SZ, 2), 256>>>();
    scanB_kernel<<<dim3(NC, NHEADS, 2 * B_SZ), 256>>>(
        f_A_log, b_A_log, f_D, b_D, f_dt_bias, b_dt_bias);

    // gate + RMS normalization (in place on y16)
    gate_rms_kernel<<<dim3(BL, 2), 128>>>(f_norm_w, b_norm_w);

    // combined projection: pre16 = x16 + proj_b + [y_f | y_b(flip)] @ wcomb^T (K=2048)
    gemm_f16<<<dim3(D_MODEL / 128, BL / 128, 1), 256, GT_SMEM>>>(
        y16, y16 + (size_t)BL * D_INNER, D_INNER,
        wcomb16, wcomb16, 2 * D_INNER,
        pre16, pre16, D_MODEL, 0,
        D_MODEL, 2 * D_INNER, D_INNER, 0b10, 0, 1, proj_b, nullptr, x16,
        nullptr, 0);

    ln_kernel<<<BL, 128>>>(ln_w, ln_b, (float*)d_out);
}